// round 1
// baseline (speedup 1.0000x reference)
#include <cuda_runtime.h>
#include <cstdint>

#define TT 64
#define BB 128
#define HH 64
#define NG 256
#define BC 64          // batch rows per CTA (128 split across 2 CTAs per layer)
#define AP 132         // smem A pitch (floats), multiple of 4 for float4 staging
#define WS_ELEMS (128*256)
#define A_ELEMS (BC*AP)
#define SMEM_BYTES ((WS_ELEMS + A_ELEMS + 64)*4)

// inter-layer h hand-off: [63 producer layers][64 t][128 b][64 h]
__device__ float g_h[63ull*64ull*128ull*64ull];
__device__ int   g_flag[63*64*2];
__device__ float g_losspart[2];

typedef unsigned long long ull;

__device__ __forceinline__ ull ffma2(ull a, ull b, ull c){
  ull d; asm("fma.rn.f32x2 %0, %1, %2, %3;" : "=l"(d) : "l"(a), "l"(b), "l"(c)); return d;
}
__device__ __forceinline__ ull splat2(float v){
  ull d; asm("mov.b64 %0, {%1, %1};" : "=l"(d) : "f"(v)); return d;
}
__device__ __forceinline__ ull pack2(float lo, float hi){
  ull d; asm("mov.b64 %0, {%1, %2};" : "=l"(d) : "f"(lo), "f"(hi)); return d;
}
__device__ __forceinline__ float2 unpack2(ull v){
  float lo, hi; asm("mov.b64 {%0, %1}, %2;" : "=f"(lo), "=f"(hi) : "l"(v));
  return make_float2(lo, hi);
}
__device__ __forceinline__ float ex2f(float x){ float y; asm("ex2.approx.f32 %0, %1;" : "=f"(y) : "f"(x)); return y; }
__device__ __forceinline__ float rcpf(float x){ float y; asm("rcp.approx.f32 %0, %1;" : "=f"(y) : "f"(x)); return y; }
__device__ __forceinline__ float sigf(float x){ return rcpf(1.0f + ex2f(-1.4426950408889634f * x)); }
__device__ __forceinline__ float tanh_f(float x){ return fmaf(2.0f, sigf(2.0f * x), -1.0f); }

__global__ void init_kernel(){
  int i = blockIdx.x * blockDim.x + threadIdx.x;
  if (i < 63*64*2) g_flag[i] = 0;
}

__global__ __launch_bounds__(256, 1)
void lstm_kernel(const float* __restrict__ x, const float* __restrict__ labels,
                 const float* __restrict__ W0, const float* __restrict__ b0,
                 const float* __restrict__ Wl, const float* __restrict__ bl,
                 const float* __restrict__ Wd, const float* __restrict__ bd,
                 float* __restrict__ out, int out_size)
{
  extern __shared__ float sm[];
  float* Ws  = sm;                       // [K][256]
  float* As  = sm + WS_ELEMS;            // [BC][AP]: cols [0..) input, then h
  float* red = As + A_ELEMS;             // [64] loss reduction scratch

  const int l    = blockIdx.x >> 1;
  const int half = blockIdx.x & 1;
  const int tid  = threadIdx.x;
  const int tx   = tid & 15;             // h-unit group: units tx*4 .. tx*4+3
  const int ty   = tid >> 4;             // batch group: rows ty*4 .. ty*4+3
  const int K    = (l == 0) ? 65 : 128;
  const int hoff = (l == 0) ? 1 : 64;

  // ---- load weights into smem (once, reused 64 timesteps) ----
  const float* Wsrc = (l == 0) ? W0 : (Wl + (size_t)(l - 1) * 128 * 256);
  {
    int n4 = K * 256 / 4;
    const float4* s4 = (const float4*)Wsrc;
    float4* d4 = (float4*)Ws;
    for (int i = tid; i < n4; i += 256) d4[i] = s4[i];
  }
  // bias into regs: bias[g][j] for column g*64 + tx*4 + j
  const float* bsrc = (l == 0) ? b0 : (bl + (size_t)(l - 1) * 256);
  float bias[4][4];
  #pragma unroll
  for (int g = 0; g < 4; g++)
    #pragma unroll
    for (int j = 0; j < 4; j++)
      bias[g][j] = bsrc[g * 64 + tx * 4 + j];

  // zero A (initial h state = 0)
  for (int i = tid; i < A_ELEMS; i += 256) As[i] = 0.0f;

  float c[4][4];
  #pragma unroll
  for (int i = 0; i < 4; i++)
    #pragma unroll
    for (int j = 0; j < 4; j++) c[i][j] = 0.0f;

  float lsum = 0.0f;
  __syncthreads();

  for (int t = 0; t < TT; t++) {
    // ---- 1. stage inputs into A cols [0, hoff) ----
    if (l == 0) {
      if (tid < BC) As[tid * AP + 0] = x[(size_t)(half * BC + tid) * TT + t];
    } else {
      if (tid == 0) {
        const int* fp = &g_flag[((l - 1) * 64 + t) * 2 + half];
        unsigned v;
        do { asm volatile("ld.acquire.gpu.b32 %0, [%1];" : "=r"(v) : "l"(fp) : "memory"); } while (v == 0u);
      }
      __syncthreads();
      const float4* src = (const float4*)&g_h[((((size_t)(l - 1) * 64 + t) * 128) + half * BC) * 64];
      for (int i = tid; i < BC * 16; i += 256) {
        int b = i >> 4, kk = i & 15;
        ((float4*)&As[b * AP])[kk] = src[i];
      }
    }
    __syncthreads();

    // ---- 2. GEMM: z[4b][16 cols] via f32x2, acc pair p = g*2+hp over cols g*64+tx*4+hp*2{+0,1}
    ull acc[4][8];
    #pragma unroll
    for (int i = 0; i < 4; i++)
      #pragma unroll
      for (int p = 0; p < 8; p++) acc[i][p] = 0ull;

    #pragma unroll 2
    for (int k = 0; k < K; k++) {
      ull a2[4];
      #pragma unroll
      for (int i = 0; i < 4; i++) a2[i] = splat2(As[(ty * 4 + i) * AP + k]);
      const float* wr = &Ws[k * 256 + tx * 4];
      #pragma unroll
      for (int g = 0; g < 4; g++) {
        float4 w = *(const float4*)(wr + g * 64);
        ull w01 = pack2(w.x, w.y);
        ull w23 = pack2(w.z, w.w);
        #pragma unroll
        for (int i = 0; i < 4; i++) {
          acc[i][g * 2 + 0] = ffma2(a2[i], w01, acc[i][g * 2 + 0]);
          acc[i][g * 2 + 1] = ffma2(a2[i], w23, acc[i][g * 2 + 1]);
        }
      }
    }

    // ---- 3. epilogue in registers: gates -> c,h ----
    float hv[4][4];
    #pragma unroll
    for (int i = 0; i < 4; i++) {
      #pragma unroll
      for (int hp = 0; hp < 2; hp++) {
        float2 zi = unpack2(acc[i][0 + hp]);
        float2 zj = unpack2(acc[i][2 + hp]);
        float2 zf = unpack2(acc[i][4 + hp]);
        float2 zo = unpack2(acc[i][6 + hp]);
        int j0 = hp * 2, j1 = hp * 2 + 1;
        {
          float vi = zi.x + bias[0][j0], vj = zj.x + bias[1][j0];
          float vf = zf.x + bias[2][j0], vo = zo.x + bias[3][j0];
          float cc = c[i][j0] * sigf(vf) + sigf(vi) * tanh_f(vj);
          c[i][j0] = cc;
          hv[i][j0] = tanh_f(cc) * sigf(vo);
        }
        {
          float vi = zi.y + bias[0][j1], vj = zj.y + bias[1][j1];
          float vf = zf.y + bias[2][j1], vo = zo.y + bias[3][j1];
          float cc = c[i][j1] * sigf(vf) + sigf(vi) * tanh_f(vj);
          c[i][j1] = cc;
          hv[i][j1] = tanh_f(cc) * sigf(vo);
        }
      }
      if (l < 63) {
        int b = ty * 4 + i;
        float4 hq = make_float4(hv[i][0], hv[i][1], hv[i][2], hv[i][3]);
        *(float4*)&g_h[((((size_t)l * 64 + t) * 128) + half * BC + b) * 64 + tx * 4] = hq;
      }
    }

    __syncthreads();   // all GEMM reads of A done -> safe to overwrite h-part

    #pragma unroll
    for (int i = 0; i < 4; i++) {
      int b = ty * 4 + i;
      #pragma unroll
      for (int j = 0; j < 4; j++) As[b * AP + hoff + tx * 4 + j] = hv[i][j];
    }
    __syncthreads();   // publish new h in smem for next step / dense head

    if (l < 63) {
      __threadfence();     // order this thread's g_h stores before flag
      __syncthreads();     // all threads fenced before tid0 releases
      if (tid == 0) {
        int* fp = &g_flag[(l * 64 + t) * 2 + half];
        asm volatile("st.release.gpu.b32 [%0], %1;" :: "l"(fp), "r"(1) : "memory");
      }
    } else {
      // fused time-distributed dense(1) + relu + loss partial
      if (tid < BC && out_size >= 8192) {
        int b = tid;
        float accd = bd[t];
        const float* hrow = &As[b * AP + hoff];
        const float* wd = &Wd[(size_t)t * HH];
        #pragma unroll
        for (int hh = 0; hh < HH; hh++) accd = fmaf(hrow[hh], wd[hh], accd);
        float pred = fmaxf(accd, 0.0f);
        int gb = half * BC + b;
        out[(size_t)gb * TT + t] = pred;
        float d = labels[(size_t)gb * TT + t] - pred;
        lsum += d * d;
      }
    }
  }

  if (l == 63) {
    if (tid < BC) red[tid] = lsum;
    __syncthreads();
    if (tid == 0) {
      float s = 0.0f;
      for (int i = 0; i < BC; i++) s += red[i];   // fixed order: deterministic
      g_losspart[half] = s;
    }
  }
}

__global__ void finish_kernel(float* out, int out_size){
  float loss = (g_losspart[0] + g_losspart[1]) * (1.0f / 8192.0f);
  if (out_size >= 8193)      out[8192] = loss;
  else if (out_size == 1)    out[0]    = loss;
}

extern "C" void kernel_launch(void* const* d_in, const int* in_sizes, int n_in,
                              void* d_out, int out_size)
{
  const float* x      = (const float*)d_in[0];
  const float* labels = (const float*)d_in[1];
  const float* W0     = (const float*)d_in[2];
  const float* b0     = (const float*)d_in[3];
  const float* Wl     = (const float*)d_in[4];
  const float* bl     = (const float*)d_in[5];
  const float* Wd     = (const float*)d_in[6];
  const float* bd     = (const float*)d_in[7];
  float* out = (float*)d_out;

  cudaFuncSetAttribute(lstm_kernel, cudaFuncAttributeMaxDynamicSharedMemorySize, SMEM_BYTES);

  init_kernel<<<32, 256>>>();
  lstm_kernel<<<128, 256, SMEM_BYTES>>>(x, labels, W0, b0, Wl, bl, Wd, bd, out, out_size);
  finish_kernel<<<1, 1>>>(out, out_size);
}

// round 3
// speedup vs baseline: 1.9277x; 1.9277x over previous
#include <cuda_runtime.h>
#include <cuda_bf16.h>
#include <cstdint>

#define TT 64
#define NB 128
#define NH 64
#define NGC 256

// Arch-feature gate: tcgen05 exists only in a compute_103a/sm_103a pass.
#if defined(__CUDA_ARCH_FEAT_SM103_ALL) || defined(__CUDA_ARCH_SPECIFIC__) || defined(__CUDA_ARCH_FAMILY_SPECIFIC__)
#define USE_TCG 1
#else
#define USE_TCG 0
#endif

// ---------------- common helpers ----------------
__device__ __forceinline__ uint32_t smem_to_u32(const void* p){
  uint32_t a; asm("{ .reg .u64 t; cvta.to.shared.u64 t, %1; cvt.u32.u64 %0, t; }" : "=r"(a) : "l"(p)); return a;
}
__device__ __forceinline__ float ex2f(float x){ float y; asm("ex2.approx.f32 %0, %1;" : "=f"(y) : "f"(x)); return y; }
__device__ __forceinline__ float rcpf(float x){ float y; asm("rcp.approx.f32 %0, %1;" : "=f"(y) : "f"(x)); return y; }
__device__ __forceinline__ float sigf(float x){ return rcpf(1.0f + ex2f(-1.4426950408889634f * x)); }
__device__ __forceinline__ float tanh_f(float x){ return fmaf(2.0f, sigf(2.0f * x), -1.0f); }

// packed h exchange: u32 = bf16_hi | bf16_lo<<16 ; [63 layers][64 t][128 b][64 u]
__device__ uint32_t g_h[63ull*64ull*128ull*64ull];
__device__ int g_flag[63*64];

#define SMEM_DYN 208896

__global__ void init_kernel(){
  int i = blockIdx.x * blockDim.x + threadIdx.x;
  if (i < 63*64) g_flag[i] = 0;
}

#if USE_TCG
// =====================================================================
// tcgen05 path (compiled only for sm_103a-capable passes)
// =====================================================================
__device__ __forceinline__ uint32_t elect_one_pred(){
  uint32_t p; asm volatile("{ .reg .pred p; elect.sync _|p, 0xFFFFFFFF; selp.b32 %0, 1, 0, p; }" : "=r"(p)); return p;
}
#define TCGEN05_ALLOC(sa, n)   asm volatile("tcgen05.alloc.cta_group::1.sync.aligned.shared::cta.b32 [%0], %1;" :: "r"((uint32_t)(sa)), "r"((uint32_t)(n)) : "memory")
#define TCGEN05_RELINQ()       asm volatile("tcgen05.relinquish_alloc_permit.cta_group::1.sync.aligned;")
#define TCGEN05_DEALLOC(t, n)  asm volatile("tcgen05.dealloc.cta_group::1.sync.aligned.b32 %0, %1;" :: "r"(t), "r"((uint32_t)(n)))
#define TCGEN05_WAIT_LD()      asm volatile("tcgen05.wait::ld.sync.aligned;" ::: "memory")
#define TCGEN05_WAIT_ST()      asm volatile("tcgen05.wait::st.sync.aligned;" ::: "memory")
#define TCGEN05_FENCE_BEFORE() asm volatile("tcgen05.fence::before_thread_sync;" ::: "memory")
#define TCGEN05_FENCE_AFTER()  asm volatile("tcgen05.fence::after_thread_sync;" ::: "memory")
#define TCGEN05_COMMIT(mb)     asm volatile("tcgen05.commit.cta_group::1.mbarrier::arrive::one.shared::cluster.b64 [%0];" :: "r"((uint32_t)(mb)) : "memory")
#define FENCE_PROXY_ASYNC()    asm volatile("fence.proxy.async.shared::cta;" ::: "memory")
#define MBARRIER_INIT(mb, n)   asm volatile("mbarrier.init.shared.b64 [%0], %1;" :: "r"((uint32_t)(mb)), "r"((uint32_t)(n)) : "memory")
#define MBARRIER_INVAL(mb)     asm volatile("mbarrier.inval.shared.b64 [%0];" :: "r"((uint32_t)(mb)) : "memory")

#define MBARRIER_WAIT_PARITY(mb, ph) do { \
  uint32_t _m = (uint32_t)(mb); uint32_t _p = (uint32_t)(ph); uint32_t _d; \
  asm volatile("{ .reg .pred p; mbarrier.try_wait.parity.acquire.cta.shared::cta.b64 p, [%1], %2; selp.b32 %0, 1, 0, p; }" \
    : "=r"(_d) : "r"(_m), "r"(_p) : "memory"); \
  if (!_d) { asm volatile("{ .reg .pred P1; WL_%=: mbarrier.try_wait.parity.acquire.cta.shared::cta.b64 P1, [%0], %1, 0x989680; @P1 bra.uni WD_%=; bra.uni WL_%=; WD_%=: }" \
    :: "r"(_m), "r"(_p) : "memory"); } \
} while(0)

#define TCGEN05_MMA_F16(d_tmem, a_tmem, b_desc, idesc, en) do { \
  uint32_t _e = (en) ? 1u : 0u; uint32_t _z = 0u; \
  asm volatile("{ .reg .pred p; setp.ne.u32 p, %6, 0; " \
    "tcgen05.mma.cta_group::1.kind::f16 [%0], [%1], %2, %3, {%4, %4, %4, %4}, p; }" \
    :: "r"(d_tmem), "r"(a_tmem), "l"(b_desc), "r"(idesc), "r"(_z), "r"(_z), "r"(_e) : "memory"); \
} while(0)

#define LDTM_X16(r, a) asm volatile( \
  "tcgen05.ld.sync.aligned.32x32b.x16.b32 {%0,%1,%2,%3,%4,%5,%6,%7,%8,%9,%10,%11,%12,%13,%14,%15}, [%16];" \
  : "=r"((r)[0]),"=r"((r)[1]),"=r"((r)[2]),"=r"((r)[3]),"=r"((r)[4]),"=r"((r)[5]),"=r"((r)[6]),"=r"((r)[7]), \
    "=r"((r)[8]),"=r"((r)[9]),"=r"((r)[10]),"=r"((r)[11]),"=r"((r)[12]),"=r"((r)[13]),"=r"((r)[14]),"=r"((r)[15]) \
  : "r"(a))

#define STTM_X8(a, r) asm volatile( \
  "tcgen05.st.sync.aligned.32x32b.x8.b32 [%0], {%1,%2,%3,%4,%5,%6,%7,%8};" \
  :: "r"(a), "r"((r)[0]),"r"((r)[1]),"r"((r)[2]),"r"((r)[3]),"r"((r)[4]),"r"((r)[5]),"r"((r)[6]),"r"((r)[7]) : "memory")

#define STTM_X1(a, v) asm volatile("tcgen05.st.sync.aligned.32x32b.x1.b32 [%0], {%1};" :: "r"(a), "r"(v) : "memory")

#define STTM_X32Z(a) do { \
  asm volatile("tcgen05.st.sync.aligned.32x32b.x32.b32 [%0], " \
   "{%1,%1,%1,%1,%1,%1,%1,%1,%1,%1,%1,%1,%1,%1,%1,%1,%1,%1,%1,%1,%1,%1,%1,%1,%1,%1,%1,%1,%1,%1,%1,%1};" \
   :: "r"(a), "r"(0u) : "memory"); \
} while(0)

static constexpr uint64_t SMEM_DESC_BASE_SW128 =
    (uint64_t(2) << 61) | (uint64_t(1) << 46) | (uint64_t(64) << 32) | (uint64_t(1) << 16);
#define MAKE_SMEM_DESC(ba) (SMEM_DESC_BASE_SW128 | ((uint64_t)((ba) >> 4) & 0x3FFF))

#define IDESC ((1u<<4)|(1u<<7)|(1u<<10)|((NGC/8)<<17)|((NB/16)<<24))

#define SM_TMEMPTR 0
#define SM_MBAR    8
#define SM_BIAS    64
#define SM_DRED    1088
#define SM_LRED    3136
#define SM_B       4096
#define TM_AHI 0
#define TM_ALO 64
#define TM_D   128

__device__ __forceinline__ uint32_t b_byte(int n, int kk){
  uint32_t off = (uint32_t)(((n >> 3) + (kk >> 6) * 32) * 1024 + (n & 7) * 128 + (kk & 63) * 2);
  return off ^ ((off >> 3) & 0x70);
}

__global__ __launch_bounds__(512, 1)
void lstm_kernel(const float* __restrict__ x, const float* __restrict__ labels,
                 const float* __restrict__ W0, const float* __restrict__ b0,
                 const float* __restrict__ Wl, const float* __restrict__ bl,
                 const float* __restrict__ Wd, const float* __restrict__ bd,
                 float* __restrict__ out, int out_size)
{
  extern __shared__ char smem[];
  const uint32_t smb = smem_to_u32(smem);
  float* smBias = (float*)(smem + SM_BIAS);
  float* dred   = (float*)(smem + SM_DRED);
  float* lred   = (float*)(smem + SM_LRED);

  const int l   = blockIdx.x;
  const int tid = threadIdx.x;
  const int w   = tid >> 5;
  const int ln  = tid & 31;
  const int s   = w & 3;
  const int q   = w >> 2;
  const int row = s * 32 + ln;
  const uint32_t woff = (uint32_t)s << 21;

  if (w == 0) TCGEN05_ALLOC(smb + SM_TMEMPTR, 512);
  __syncthreads();
  uint32_t tb;
  asm volatile("ld.shared.b32 %0, [%1];" : "=r"(tb) : "r"(smb + SM_TMEMPTR));
  if (w == 0) TCGEN05_RELINQ();

  for (int idx = tid; idx < 128 * 256; idx += 512) {
    int k = idx >> 8, n = idx & 255;
    float wv;
    if (l == 0) {
      if (k < 64)       wv = W0[(1 + k) * 256 + n];
      else if (k == 64) wv = W0[n];
      else              wv = 0.0f;
    } else {
      wv = Wl[(size_t)(l - 1) * 128 * 256 + (size_t)k * 256 + n];
    }
    __nv_bfloat16 bh = __float2bfloat16_rn(wv);
    __nv_bfloat16 blo = __float2bfloat16_rn(wv - __bfloat162float(bh));
    *(__nv_bfloat16*)(smem + SM_B + b_byte(n, k))       = bh;
    *(__nv_bfloat16*)(smem + SM_B + b_byte(n, 128 + k)) = blo;
  }
  {
    const float* bs = (l == 0) ? b0 : (bl + (size_t)(l - 1) * 256);
    for (int i = tid; i < 256; i += 512) smBias[i] = bs[i];
  }
  if (tid == 0) MBARRIER_INIT(smb + SM_MBAR, 1);

  STTM_X32Z(tb + q * 32 + woff);
  TCGEN05_WAIT_ST();
  FENCE_PROXY_ASYNC();
  TCGEN05_FENCE_BEFORE();
  __syncthreads();

  const uint64_t bdesc0 = MAKE_SMEM_DESC(smb + SM_B);
  const int own_hi = (l == 0) ? TM_AHI : (TM_AHI + 32);
  const int own_lo = own_hi + 64;
  const int q16 = q * 16, q8 = q * 8;

  float c[16];
  #pragma unroll
  for (int i = 0; i < 16; i++) c[i] = 0.0f;
  float bias_r[4][16];
  #pragma unroll
  for (int g = 0; g < 4; g++)
    #pragma unroll
    for (int uu = 0; uu < 16; uu++) bias_r[g][uu] = smBias[g * 64 + q16 + uu];

  float lsum = 0.0f;

  for (int t = 0; t < TT; t++) {
    if (l > 0) {
      if (tid == 0) {
        const int* fp = &g_flag[(l - 1) * 64 + t];
        unsigned v;
        do { asm volatile("ld.acquire.gpu.b32 %0, [%1];" : "=r"(v) : "l"(fp) : "memory"); } while (v == 0u);
      }
      __syncthreads();
      const uint4* src = (const uint4*)&g_h[(((size_t)(l - 1) * 64 + t) * 128 + row) * 64 + q16];
      uint32_t pk[16];
      #pragma unroll
      for (int m = 0; m < 4; m++) {
        uint4 v = src[m];
        pk[m*4+0] = v.x; pk[m*4+1] = v.y; pk[m*4+2] = v.z; pk[m*4+3] = v.w;
      }
      uint32_t wh[8], wlo[8];
      #pragma unroll
      for (int m = 0; m < 8; m++) {
        uint32_t p0 = pk[2*m], p1 = pk[2*m+1];
        wh[m]  = (p0 & 0xFFFFu) | (p1 << 16);
        wlo[m] = (p0 >> 16)     | (p1 & 0xFFFF0000u);
      }
      STTM_X8(tb + TM_AHI + q8 + woff, wh);
      STTM_X8(tb + TM_ALO + q8 + woff, wlo);
      TCGEN05_WAIT_ST();
    } else {
      if (q == 0) {
        float xv = x[(size_t)row * TT + t];
        __nv_bfloat16 xh = __float2bfloat16_rn(xv);
        __nv_bfloat16 xl = __float2bfloat16_rn(xv - __bfloat162float(xh));
        STTM_X1(tb + 32 + woff, (uint32_t)__bfloat16_as_ushort(xh));
        STTM_X1(tb + 96 + woff, (uint32_t)__bfloat16_as_ushort(xl));
        TCGEN05_WAIT_ST();
      }
    }
    TCGEN05_FENCE_BEFORE();
    __syncthreads();

    if (w == 0) {
      TCGEN05_FENCE_AFTER();
      if (elect_one_pred()) {
        #pragma unroll
        for (int c8 = 0; c8 < 8; c8++) {
          uint64_t bh_d = bdesc0 + (uint64_t)((c8 >> 2) * 2048 + (c8 & 3) * 2);
          uint64_t bl_d = bdesc0 + (uint64_t)((((c8 + 8) >> 2)) * 2048 + (c8 & 3) * 2);
          TCGEN05_MMA_F16(tb + TM_D, tb + TM_AHI + c8 * 8, bh_d, IDESC, c8 > 0);
          TCGEN05_MMA_F16(tb + TM_D, tb + TM_ALO + c8 * 8, bh_d, IDESC, true);
          TCGEN05_MMA_F16(tb + TM_D, tb + TM_AHI + c8 * 8, bl_d, IDESC, true);
        }
        TCGEN05_COMMIT(smb + SM_MBAR);
      }
    }
    MBARRIER_WAIT_PARITY(smb + SM_MBAR, t & 1);
    TCGEN05_FENCE_AFTER();

    uint32_t ra[16], rb[16];
    float aij[16];
    LDTM_X16(ra, tb + TM_D + 0 * 64 + q16 + woff);
    LDTM_X16(rb, tb + TM_D + 1 * 64 + q16 + woff);
    TCGEN05_WAIT_LD();
    #pragma unroll
    for (int uu = 0; uu < 16; uu++) {
      float vi = __uint_as_float(ra[uu]) + bias_r[0][uu];
      float vj = __uint_as_float(rb[uu]) + bias_r[1][uu];
      aij[uu] = sigf(vi) * tanh_f(vj);
    }
    LDTM_X16(ra, tb + TM_D + 2 * 64 + q16 + woff);
    LDTM_X16(rb, tb + TM_D + 3 * 64 + q16 + woff);
    TCGEN05_WAIT_LD();
    float h[16];
    #pragma unroll
    for (int uu = 0; uu < 16; uu++) {
      float vf = __uint_as_float(ra[uu]) + bias_r[2][uu];
      float vo = __uint_as_float(rb[uu]) + bias_r[3][uu];
      float cc = c[uu] * sigf(vf) + aij[uu];
      c[uu] = cc;
      h[uu] = tanh_f(cc) * sigf(vo);
    }

    uint32_t pk[16];
    #pragma unroll
    for (int uu = 0; uu < 16; uu++) {
      __nv_bfloat16 hh = __float2bfloat16_rn(h[uu]);
      __nv_bfloat16 hl = __float2bfloat16_rn(h[uu] - __bfloat162float(hh));
      pk[uu] = (uint32_t)__bfloat16_as_ushort(hh) | ((uint32_t)__bfloat16_as_ushort(hl) << 16);
    }
    {
      uint32_t wh[8], wlo[8];
      #pragma unroll
      for (int m = 0; m < 8; m++) {
        uint32_t p0 = pk[2*m], p1 = pk[2*m+1];
        wh[m]  = (p0 & 0xFFFFu) | (p1 << 16);
        wlo[m] = (p0 >> 16)     | (p1 & 0xFFFF0000u);
      }
      STTM_X8(tb + own_hi + q8 + woff, wh);
      STTM_X8(tb + own_lo + q8 + woff, wlo);
      TCGEN05_WAIT_ST();
    }
    TCGEN05_FENCE_BEFORE();

    if (l < 63) {
      uint4* dst = (uint4*)&g_h[(((size_t)l * 64 + t) * 128 + row) * 64 + q16];
      #pragma unroll
      for (int m = 0; m < 4; m++)
        dst[m] = make_uint4(pk[m*4+0], pk[m*4+1], pk[m*4+2], pk[m*4+3]);
      __threadfence();
      __syncthreads();
      if (tid == 0) {
        int* fp = &g_flag[l * 64 + t];
        asm volatile("st.release.gpu.b32 [%0], %1;" :: "l"(fp), "r"(1) : "memory");
      }
    } else {
      float part = 0.0f;
      const float4* wd4 = (const float4*)&Wd[(size_t)t * NH + q16];
      #pragma unroll
      for (int m = 0; m < 4; m++) {
        float4 wv = wd4[m];
        part += h[m*4+0]*wv.x + h[m*4+1]*wv.y + h[m*4+2]*wv.z + h[m*4+3]*wv.w;
      }
      dred[row * 4 + q] = part;
      __syncthreads();
      if (w < 4) {
        float p = dred[row*4+0] + dred[row*4+1] + dred[row*4+2] + dred[row*4+3] + bd[t];
        float pred = fmaxf(p, 0.0f);
        if (out_size >= 8192) out[(size_t)row * TT + t] = pred;
        float d = labels[(size_t)row * TT + t] - pred;
        lsum += d * d;
      }
      __syncthreads();
    }
  }

  if (l == 63) {
    if (w < 4) lred[row] = lsum;
    __syncthreads();
    if (tid == 0) {
      float ssum = 0.0f;
      for (int i = 0; i < 128; i++) ssum += lred[i];
      float loss = ssum * (1.0f / 8192.0f);
      if (out_size >= 8193)   out[8192] = loss;
      else if (out_size == 1) out[0] = loss;
    }
  }

  __syncthreads();
  if (tid == 0) MBARRIER_INVAL(smb + SM_MBAR);
  __syncthreads();
  if (w == 0) TCGEN05_DEALLOC(tb, 512);
}

#else
// =====================================================================
// HMMA fallback path (plain sm_103 — warp-level mma.sync, bf16 3-term)
// =====================================================================
#define AS 136   // A row stride in bf16 (272 B: conflict-free LDSM)
#define WS 264   // W row stride in bf16 (528 B)
#define HB_BIAS 0
#define HB_LRED 3072
#define HB_AH   4096
#define HB_AL   (HB_AH + 128*AS*2)      // 38912
#define HB_WH   73728
#define HB_WL   (HB_WH + 128*WS*2)      // 141312

#define LDSM_X4(r, a) asm volatile("ldmatrix.sync.aligned.m8n8.x4.shared.b16 {%0,%1,%2,%3}, [%4];" \
  : "=r"((r)[0]),"=r"((r)[1]),"=r"((r)[2]),"=r"((r)[3]) : "r"(a))
#define LDSM_X4T(r, a) asm volatile("ldmatrix.sync.aligned.m8n8.x4.trans.shared.b16 {%0,%1,%2,%3}, [%4];" \
  : "=r"((r)[0]),"=r"((r)[1]),"=r"((r)[2]),"=r"((r)[3]) : "r"(a))
#define MMA16816(d, a, b0v, b1v) asm volatile( \
  "mma.sync.aligned.m16n8k16.row.col.f32.bf16.bf16.f32 {%0,%1,%2,%3}, {%4,%5,%6,%7}, {%8,%9}, {%0,%1,%2,%3};" \
  : "+f"((d)[0]),"+f"((d)[1]),"+f"((d)[2]),"+f"((d)[3]) \
  : "r"((a)[0]),"r"((a)[1]),"r"((a)[2]),"r"((a)[3]), "r"(b0v),"r"(b1v))

__global__ __launch_bounds__(512, 1)
void lstm_kernel(const float* __restrict__ x, const float* __restrict__ labels,
                 const float* __restrict__ W0, const float* __restrict__ b0,
                 const float* __restrict__ Wl, const float* __restrict__ bl,
                 const float* __restrict__ Wd, const float* __restrict__ bd,
                 float* __restrict__ out, int out_size)
{
  extern __shared__ char smem[];
  const uint32_t smb = smem_to_u32(smem);
  float* biasS = (float*)(smem + HB_BIAS);
  float* lred  = (float*)(smem + HB_LRED);

  const int l   = blockIdx.x;
  const int tid = threadIdx.x;
  const int w   = tid >> 5;
  const int ln  = tid & 31;
  const int mg  = w & 3;     // rows mg*32 .. +31
  const int qu  = w >> 2;    // units qu*16 .. +15
  const int tq  = ln >> 2, tr = ln & 3;
  const int ownk = (l == 0) ? 0 : 64;

  // ---- build split weights in SMEM (once) ----
  for (int idx = tid; idx < 128 * 256; idx += 512) {
    int k = idx >> 8, n = idx & 255;
    float wv;
    if (l == 0) wv = (k < 64) ? W0[(1 + k) * 256 + n] : (k == 64 ? W0[n] : 0.0f);
    else        wv = Wl[(size_t)(l - 1) * 32768 + (size_t)k * 256 + n];
    __nv_bfloat16 bh  = __float2bfloat16_rn(wv);
    __nv_bfloat16 bl2 = __float2bfloat16_rn(wv - __bfloat162float(bh));
    *(__nv_bfloat16*)(smem + HB_WH + ((size_t)k * WS + n) * 2) = bh;
    *(__nv_bfloat16*)(smem + HB_WL + ((size_t)k * WS + n) * 2) = bl2;
  }
  {
    const float* bs = (l == 0) ? b0 : (bl + (size_t)(l - 1) * 256);
    for (int i = tid; i < 256; i += 512) biasS[i] = bs[i];
  }
  // zero both A buffers (initial h = 0, pads)
  for (int i = tid; i < (128 * AS * 2 * 2) / 4; i += 512)
    ((uint32_t*)(smem + HB_AH))[i] = 0u;
  __syncthreads();

  // bias regs: bsr[g][h8*2+j] for u = qu*16 + h8*8 + tr*2 + j
  float bsr[4][4];
  #pragma unroll
  for (int g = 0; g < 4; g++)
    #pragma unroll
    for (int h8 = 0; h8 < 2; h8++)
      #pragma unroll
      for (int j = 0; j < 2; j++)
        bsr[g][h8*2+j] = biasS[g * 64 + qu * 16 + h8 * 8 + tr * 2 + j];

  float cst[16];
  #pragma unroll
  for (int i = 0; i < 16; i++) cst[i] = 0.0f;
  float lsum = 0.0f;

  for (int t = 0; t < TT; t++) {
    // ---- stage inputs ----
    if (l > 0 && tid == 0) {
      const int* fp = &g_flag[(l - 1) * 64 + t];
      unsigned v;
      do { asm volatile("ld.acquire.gpu.b32 %0, [%1];" : "=r"(v) : "l"(fp) : "memory"); } while (v == 0u);
    }
    __syncthreads();
    if (l > 0) {
      int b = tid >> 2, ug = (tid & 3) * 16;
      const uint2* src = (const uint2*)&g_h[(((size_t)(l - 1) * 64 + t) * 128 + b) * 64 + ug];
      char* da = smem + HB_AH + ((size_t)b * AS + ug) * 2;
      char* dl = smem + HB_AL + ((size_t)b * AS + ug) * 2;
      #pragma unroll
      for (int m = 0; m < 8; m++) {
        uint2 v = src[m];
        *(uint32_t*)(da + m * 4) = (v.x & 0xFFFFu) | (v.y << 16);
        *(uint32_t*)(dl + m * 4) = (v.x >> 16) | (v.y & 0xFFFF0000u);
      }
    } else if (tid < 128) {
      float xv = x[(size_t)tid * TT + t];
      __nv_bfloat16 xh = __float2bfloat16_rn(xv);
      __nv_bfloat16 xl = __float2bfloat16_rn(xv - __bfloat162float(xh));
      *(__nv_bfloat16*)(smem + HB_AH + ((size_t)tid * AS + 64) * 2) = xh;
      *(__nv_bfloat16*)(smem + HB_AL + ((size_t)tid * AS + 64) * 2) = xl;
    }
    __syncthreads();

    // ---- GEMM: 3 passes (Ah*Wh, Al*Wh, Ah*Wl) ----
    float acc[4][2][2][4];
    #pragma unroll
    for (int g = 0; g < 4; g++)
      #pragma unroll
      for (int h8 = 0; h8 < 2; h8++)
        #pragma unroll
        for (int mt = 0; mt < 2; mt++)
          #pragma unroll
          for (int cix = 0; cix < 4; cix++) acc[g][h8][mt][cix] = 0.0f;

    const uint32_t aB[3] = {smb + HB_AH, smb + HB_AL, smb + HB_AH};
    const uint32_t wB[3] = {smb + HB_WH, smb + HB_WH, smb + HB_WL};
    #pragma unroll
    for (int ps = 0; ps < 3; ps++) {
      uint32_t Ab = aB[ps], Wb = wB[ps];
      #pragma unroll
      for (int kk = 0; kk < 8; kk++) {
        uint32_t afr[2][4];
        uint32_t ar = Ab + (uint32_t)(((mg * 32 + (ln & 15)) * AS + kk * 16 + ((ln >> 4) << 3)) * 2);
        LDSM_X4(afr[0], ar);
        LDSM_X4(afr[1], ar + 16 * AS * 2);
        uint32_t br = Wb + (uint32_t)(((kk * 16 + (ln & 15)) * WS + qu * 16 + ((ln >> 4) << 3)) * 2);
        #pragma unroll
        for (int g = 0; g < 4; g++) {
          uint32_t bfr[4];
          LDSM_X4T(bfr, br + g * 128);
          MMA16816(acc[g][0][0], afr[0], bfr[0], bfr[1]);
          MMA16816(acc[g][0][1], afr[1], bfr[0], bfr[1]);
          MMA16816(acc[g][1][0], afr[0], bfr[2], bfr[3]);
          MMA16816(acc[g][1][1], afr[1], bfr[2], bfr[3]);
        }
      }
    }

    // ---- cell update fully in registers ----
    float hv[16];
    #pragma unroll
    for (int mt = 0; mt < 2; mt++)
      #pragma unroll
      for (int rh = 0; rh < 2; rh++)
        #pragma unroll
        for (int h8 = 0; h8 < 2; h8++)
          #pragma unroll
          for (int j = 0; j < 2; j++) {
            int ci = rh * 2 + j;
            int ii = mt * 8 + rh * 4 + h8 * 2 + j;
            float vi = acc[0][h8][mt][ci] + bsr[0][h8*2+j];
            float vj = acc[1][h8][mt][ci] + bsr[1][h8*2+j];
            float vf = acc[2][h8][mt][ci] + bsr[2][h8*2+j];
            float vo = acc[3][h8][mt][ci] + bsr[3][h8*2+j];
            float cc = cst[ii] * sigf(vf) + sigf(vi) * tanh_f(vj);
            cst[ii] = cc;
            hv[ii] = tanh_f(cc) * sigf(vo);
          }

    __syncthreads();   // all GEMM reads of A done before overwriting own-h

    #pragma unroll
    for (int mt = 0; mt < 2; mt++)
      #pragma unroll
      for (int rh = 0; rh < 2; rh++) {
        int b = mg * 32 + mt * 16 + tq + rh * 8;
        #pragma unroll
        for (int h8 = 0; h8 < 2; h8++) {
          int i0 = mt * 8 + rh * 4 + h8 * 2;
          float h0 = hv[i0], h1 = hv[i0 + 1];
          __nv_bfloat16 a0 = __float2bfloat16_rn(h0);
          __nv_bfloat16 a1 = __float2bfloat16_rn(h1);
          __nv_bfloat16 l0b = __float2bfloat16_rn(h0 - __bfloat162float(a0));
          __nv_bfloat16 l1b = __float2bfloat16_rn(h1 - __bfloat162float(a1));
          uint32_t hi0 = __bfloat16_as_ushort(a0), hi1 = __bfloat16_as_ushort(a1);
          uint32_t lo0 = __bfloat16_as_ushort(l0b), lo1 = __bfloat16_as_ushort(l1b);
          int u = qu * 16 + h8 * 8 + tr * 2;
          *(uint32_t*)(smem + HB_AH + ((size_t)b * AS + ownk + u) * 2) = hi0 | (hi1 << 16);
          *(uint32_t*)(smem + HB_AL + ((size_t)b * AS + ownk + u) * 2) = lo0 | (lo1 << 16);
          if (l < 63) {
            uint2 pv = make_uint2(hi0 | (lo0 << 16), hi1 | (lo1 << 16));
            *(uint2*)&g_h[(((size_t)l * 64 + t) * 128 + b) * 64 + u] = pv;
          }
        }
      }

    if (l < 63) __threadfence();
    __syncthreads();

    if (l < 63) {
      if (tid == 0) {
        int* fp = &g_flag[l * 64 + t];
        asm volatile("st.release.gpu.b32 [%0], %1;" :: "l"(fp), "r"(1) : "memory");
      }
    } else if (tid < 128) {
      int b = tid;
      float accd = bd[t];
      const uint32_t* hp = (const uint32_t*)(smem + HB_AH + ((size_t)b * AS + ownk) * 2);
      const uint32_t* lp = (const uint32_t*)(smem + HB_AL + ((size_t)b * AS + ownk) * 2);
      const float* wd = &Wd[(size_t)t * 64];
      #pragma unroll 8
      for (int i2 = 0; i2 < 32; i2++) {
        uint32_t hh = hp[i2], lv = lp[i2];
        float h0 = __bfloat162float(__ushort_as_bfloat16((unsigned short)(hh & 0xFFFF)))
                 + __bfloat162float(__ushort_as_bfloat16((unsigned short)(lv & 0xFFFF)));
        float h1 = __bfloat162float(__ushort_as_bfloat16((unsigned short)(hh >> 16)))
                 + __bfloat162float(__ushort_as_bfloat16((unsigned short)(lv >> 16)));
        accd += h0 * wd[2*i2] + h1 * wd[2*i2+1];
      }
      float pred = fmaxf(accd, 0.0f);
      if (out_size >= 8192) out[(size_t)b * TT + t] = pred;
      float d = labels[(size_t)b * TT + t] - pred;
      lsum += d * d;
    }
  }

  if (l == 63) {
    if (tid < 128) lred[tid] = lsum;
    __syncthreads();
    if (tid == 0) {
      float ssum = 0.0f;
      for (int i = 0; i < 128; i++) ssum += lred[i];
      float loss = ssum * (1.0f / 8192.0f);
      if (out_size >= 8193)   out[8192] = loss;
      else if (out_size == 1) out[0] = loss;
    }
  }
}
#endif  // USE_TCG

extern "C" void kernel_launch(void* const* d_in, const int* in_sizes, int n_in,
                              void* d_out, int out_size)
{
  const float* x      = (const float*)d_in[0];
  const float* labels = (const float*)d_in[1];
  const float* W0     = (const float*)d_in[2];
  const float* b0     = (const float*)d_in[3];
  const float* Wl     = (const float*)d_in[4];
  const float* bl     = (const float*)d_in[5];
  const float* Wd     = (const float*)d_in[6];
  const float* bd     = (const float*)d_in[7];
  float* out = (float*)d_out;

  cudaFuncSetAttribute(lstm_kernel, cudaFuncAttributeMaxDynamicSharedMemorySize, SMEM_DYN);

  init_kernel<<<16, 256>>>();
  lstm_kernel<<<64, 512, SMEM_DYN>>>(x, labels, W0, b0, Wl, bl, Wd, bd, out, out_size);
}

// round 4
// speedup vs baseline: 3.2992x; 1.7115x over previous
#include <cuda_runtime.h>
#include <cuda_bf16.h>
#include <cstdint>

#define TT 64
#define AS 136   // A row stride (bf16 elems) -> 272 B
#define WS 264   // W row stride (bf16 elems) -> 528 B

// SMEM byte offsets
#define SM_BIAS 0                        // 256 f32
#define SM_LRED 1024                     // 64 f32
#define SM_AH   1536                     // A hi: 64 x AS bf16 = 17408 B
#define SM_AL   (SM_AH + 64*AS*2)
#define SM_WH   (SM_AL + 64*AS*2)        // W hi: 128 x WS bf16 = 67584 B
#define SM_WL   (SM_WH + 128*WS*2)
#define SMEM_DYN (SM_WL + 128*WS*2)      // 171520 B

// packed h exchange: u32 = bf16_hi | bf16_lo<<16 ; [63 layers][64 t][128 b][64 u]
__device__ uint32_t g_h[63ull*64ull*128ull*64ull];
__device__ int g_flag[63*64*2];
__device__ float g_losspart[2];

__device__ __forceinline__ uint32_t smem_to_u32(const void* p){
  uint32_t a; asm("{ .reg .u64 t; cvta.to.shared.u64 t, %1; cvt.u32.u64 %0, t; }" : "=r"(a) : "l"(p)); return a;
}
__device__ __forceinline__ float tanha(float x){
  float y; asm("tanh.approx.f32 %0, %1;" : "=f"(y) : "f"(x)); return y;
}
__device__ __forceinline__ float siga(float x){
  return fmaf(0.5f, tanha(0.5f * x), 0.5f);
}

#define LDSM_X4(r, a) asm volatile("ldmatrix.sync.aligned.m8n8.x4.shared.b16 {%0,%1,%2,%3}, [%4];" \
  : "=r"((r)[0]),"=r"((r)[1]),"=r"((r)[2]),"=r"((r)[3]) : "r"(a))
#define LDSM_X2T(r, a) asm volatile("ldmatrix.sync.aligned.m8n8.x2.trans.shared.b16 {%0,%1}, [%2];" \
  : "=r"((r)[0]),"=r"((r)[1]) : "r"(a))
#define MMA16816(d, a, b0v, b1v) asm volatile( \
  "mma.sync.aligned.m16n8k16.row.col.f32.bf16.bf16.f32 {%0,%1,%2,%3}, {%4,%5,%6,%7}, {%8,%9}, {%0,%1,%2,%3};" \
  : "+f"((d)[0]),"+f"((d)[1]),"+f"((d)[2]),"+f"((d)[3]) \
  : "r"((a)[0]),"r"((a)[1]),"r"((a)[2]),"r"((a)[3]), "r"(b0v),"r"(b1v))

__global__ void init_kernel(){
  int i = blockIdx.x * blockDim.x + threadIdx.x;
  if (i < 63*64*2) g_flag[i] = 0;
  if (i < 2) g_losspart[i] = 0.0f;
}

// One K=64 slab of the 3-term split GEMM: acc += A[:, kbase..kbase+63] @ W[kbase.., :]
__device__ __forceinline__ void gemm_part(uint32_t smb, int kbase, int mg, int qu, int ln,
                                          float acc[2][4][4]){
  #pragma unroll
  for (int kk = 0; kk < 4; kk++){
    const int k0 = kbase + kk * 16;
    const uint32_t aoff = (uint32_t)(((mg * 32 + (ln & 15)) * AS + k0 + ((ln >> 4) << 3)) * 2);
    uint32_t ah[2][4], al[2][4];
    LDSM_X4(ah[0], smb + SM_AH + aoff);
    LDSM_X4(ah[1], smb + SM_AH + aoff + 16 * AS * 2);
    LDSM_X4(al[0], smb + SM_AL + aoff);
    LDSM_X4(al[1], smb + SM_AL + aoff + 16 * AS * 2);
    const uint32_t brow = (uint32_t)(k0 + (ln & 15));
    #pragma unroll
    for (int g = 0; g < 4; g++){
      const uint32_t boff = (brow * WS + g * 64 + qu * 8) * 2;
      uint32_t bh[2], bl2[2];
      LDSM_X2T(bh,  smb + SM_WH + boff);
      LDSM_X2T(bl2, smb + SM_WL + boff);
      #pragma unroll
      for (int mt = 0; mt < 2; mt++){
        MMA16816(acc[mt][g], ah[mt], bh[0],  bh[1]);    // Ahi * Whi
        MMA16816(acc[mt][g], al[mt], bh[0],  bh[1]);    // Alo * Whi
        MMA16816(acc[mt][g], ah[mt], bl2[0], bl2[1]);   // Ahi * Wlo
      }
    }
  }
}

__global__ __launch_bounds__(512, 1)
void lstm_kernel(const float* __restrict__ x, const float* __restrict__ labels,
                 const float* __restrict__ W0, const float* __restrict__ b0,
                 const float* __restrict__ Wl, const float* __restrict__ bl,
                 const float* __restrict__ Wd, const float* __restrict__ bd,
                 float* __restrict__ out, int out_size)
{
  extern __shared__ char smem[];
  const uint32_t smb = smem_to_u32(smem);
  float* biasS = (float*)(smem + SM_BIAS);
  float* lred  = (float*)(smem + SM_LRED);

  const int l    = blockIdx.x >> 1;
  const int half = blockIdx.x & 1;
  const int tid  = threadIdx.x;
  const int w    = tid >> 5;
  const int ln   = tid & 31;
  const int mg   = w & 1;          // row block: rows mg*32 .. +31 (local, of 64)
  const int qu   = w >> 1;         // unit block: units qu*8 .. +7
  const int tq   = ln >> 2, tr = ln & 3;
  const int u0   = qu * 8 + tr * 2;

  // ---- build split weights in SMEM (once). our k: [own h 0..63 | lower/x 64..127]
  for (int idx = tid; idx < 32768; idx += 512){
    int k = idx >> 8, n = idx & 255;
    float wv;
    if (l == 0) wv = (k < 64) ? W0[(1 + k) * 256 + n] : (k == 64 ? W0[n] : 0.0f);
    else {
      const float* Wsrc = Wl + (size_t)(l - 1) * 32768;
      wv = (k < 64) ? Wsrc[(64 + k) * 256 + n] : Wsrc[(k - 64) * 256 + n];
    }
    __nv_bfloat16 bh  = __float2bfloat16_rn(wv);
    __nv_bfloat16 bl2 = __float2bfloat16_rn(wv - __bfloat162float(bh));
    *(__nv_bfloat16*)(smem + SM_WH + ((size_t)k * WS + n) * 2) = bh;
    *(__nv_bfloat16*)(smem + SM_WL + ((size_t)k * WS + n) * 2) = bl2;
  }
  {
    const float* bs = (l == 0) ? b0 : bl + (size_t)(l - 1) * 256;
    for (int i = tid; i < 256; i += 512) biasS[i] = bs[i];
  }
  for (int i = tid; i < (64 * AS * 2 * 2) / 4; i += 512)
    ((uint32_t*)(smem + SM_AH))[i] = 0u;
  __syncthreads();

  float bsr[4][2];
  #pragma unroll
  for (int g = 0; g < 4; g++)
    #pragma unroll
    for (int j = 0; j < 2; j++) bsr[g][j] = biasS[g * 64 + u0 + j];

  float cst[8];
  #pragma unroll
  for (int i = 0; i < 8; i++) cst[i] = 0.0f;
  float lsum = 0.0f;

  for (int t = 0; t < TT; t++){
    // ---- 1. own-h GEMM (off critical path; uses h_{t-1} in A cols 0..63) ----
    float acc[2][4][4];
    #pragma unroll
    for (int mt = 0; mt < 2; mt++)
      #pragma unroll
      for (int g = 0; g < 4; g++)
        #pragma unroll
        for (int ci = 0; ci < 4; ci++) acc[mt][g][ci] = 0.0f;
    gemm_part(smb, 0, mg, qu, ln, acc);

    // ---- 2. wait lower h, stage into A cols 64..127 ----
    if (l > 0){
      const int* fp = &g_flag[((l - 1) * 64 + t) * 2 + half];
      unsigned v;
      do { asm volatile("ld.acquire.gpu.b32 %0, [%1];" : "=r"(v) : "l"(fp) : "memory"); } while (v == 0u);
      const int r = tid >> 3, c8 = (tid & 7) * 8;
      const uint4* src = (const uint4*)&g_h[((((size_t)(l - 1) * 64 + t) * 128) + half * 64 + r) * 64 + c8];
      uint4 v0 = src[0], v1 = src[1];
      uint32_t pa[8] = {v0.x, v0.y, v0.z, v0.w, v1.x, v1.y, v1.z, v1.w};
      uint32_t hi[4], lo[4];
      #pragma unroll
      for (int m = 0; m < 4; m++){
        uint32_t a = pa[2*m], b = pa[2*m+1];
        hi[m] = (a & 0xFFFFu) | (b << 16);
        lo[m] = (a >> 16)     | (b & 0xFFFF0000u);
      }
      *(uint4*)(smem + SM_AH + (r * AS + 64 + c8) * 2) = make_uint4(hi[0], hi[1], hi[2], hi[3]);
      *(uint4*)(smem + SM_AL + (r * AS + 64 + c8) * 2) = make_uint4(lo[0], lo[1], lo[2], lo[3]);
    } else {
      if (tid < 64){
        float xv = x[(size_t)(half * 64 + tid) * TT + t];
        __nv_bfloat16 xh = __float2bfloat16_rn(xv);
        __nv_bfloat16 xl = __float2bfloat16_rn(xv - __bfloat162float(xh));
        *(__nv_bfloat16*)(smem + SM_AH + (tid * AS + 64) * 2) = xh;
        *(__nv_bfloat16*)(smem + SM_AL + (tid * AS + 64) * 2) = xl;
      }
    }
    __syncthreads();

    // ---- 3. x-part GEMM (critical path) ----
    gemm_part(smb, 64, mg, qu, ln, acc);

    // ---- 4. epilogue: gates -> c, h (8 cells/thread) ----
    float hv[8];
    #pragma unroll
    for (int mt = 0; mt < 2; mt++)
      #pragma unroll
      for (int ci = 0; ci < 4; ci++){
        const int j = ci & 1;
        const int ii = mt * 4 + ci;
        float vi = acc[mt][0][ci] + bsr[0][j];
        float vj = acc[mt][1][ci] + bsr[1][j];
        float vf = acc[mt][2][ci] + bsr[2][j];
        float vo = acc[mt][3][ci] + bsr[3][j];
        float cc = cst[ii] * siga(vf) + siga(vi) * tanha(vj);
        cst[ii] = cc;
        hv[ii] = tanha(cc) * siga(vo);
      }

    // ---- 5. store h to A_own (cols 0..63) + publish to g_h ----
    #pragma unroll
    for (int mt = 0; mt < 2; mt++)
      #pragma unroll
      for (int rh = 0; rh < 2; rh++){
        const int b = mg * 32 + mt * 16 + tq + rh * 8;
        const int i0 = mt * 4 + rh * 2;
        float h0 = hv[i0], h1 = hv[i0 + 1];
        __nv_bfloat16 a0 = __float2bfloat16_rn(h0);
        __nv_bfloat16 a1 = __float2bfloat16_rn(h1);
        __nv_bfloat16 l0 = __float2bfloat16_rn(h0 - __bfloat162float(a0));
        __nv_bfloat16 l1 = __float2bfloat16_rn(h1 - __bfloat162float(a1));
        uint32_t hi0 = __bfloat16_as_ushort(a0), hi1 = __bfloat16_as_ushort(a1);
        uint32_t lo0 = __bfloat16_as_ushort(l0), lo1 = __bfloat16_as_ushort(l1);
        *(uint32_t*)(smem + SM_AH + (b * AS + u0) * 2) = hi0 | (hi1 << 16);
        *(uint32_t*)(smem + SM_AL + (b * AS + u0) * 2) = lo0 | (lo1 << 16);
        if (l < 63){
          *(uint2*)&g_h[(((size_t)l * 64 + t) * 128 + half * 64 + b) * 64 + u0] =
            make_uint2(hi0 | (lo0 << 16), hi1 | (lo1 << 16));
        }
      }

    if (l < 63) __threadfence();
    __syncthreads();
    if (l < 63){
      if (tid == 0){
        int* fp = &g_flag[(l * 64 + t) * 2 + half];
        asm volatile("st.release.gpu.b32 [%0], %1;" :: "l"(fp), "r"(1) : "memory");
      }
    } else if (tid < 64){
      // fused dense(1) + relu + loss partial for this CTA's 64 rows
      const int r = tid;
      float accd = bd[t];
      const uint32_t* hp = (const uint32_t*)(smem + SM_AH + r * AS * 2);
      const uint32_t* lp = (const uint32_t*)(smem + SM_AL + r * AS * 2);
      const float* wd = &Wd[(size_t)t * 64];
      #pragma unroll 8
      for (int i2 = 0; i2 < 32; i2++){
        uint32_t hh = hp[i2], lv = lp[i2];
        float h0 = __bfloat162float(__ushort_as_bfloat16((unsigned short)(hh & 0xFFFF)))
                 + __bfloat162float(__ushort_as_bfloat16((unsigned short)(lv & 0xFFFF)));
        float h1 = __bfloat162float(__ushort_as_bfloat16((unsigned short)(hh >> 16)))
                 + __bfloat162float(__ushort_as_bfloat16((unsigned short)(lv >> 16)));
        accd += h0 * wd[2*i2] + h1 * wd[2*i2+1];
      }
      float pred = fmaxf(accd, 0.0f);
      const int gb = half * 64 + r;
      if (out_size >= 8192) out[(size_t)gb * TT + t] = pred;
      float d = labels[(size_t)gb * TT + t] - pred;
      lsum += d * d;
    }
  }

  if (l == 63){
    if (tid < 64) lred[tid] = lsum;
    __syncthreads();
    if (tid == 0){
      float s = 0.0f;
      for (int i = 0; i < 64; i++) s += lred[i];   // fixed order: deterministic
      g_losspart[half] = s;
    }
  }
}

__global__ void finish_kernel(float* out, int out_size){
  float loss = (g_losspart[0] + g_losspart[1]) * (1.0f / 8192.0f);
  if (out_size >= 8193)      out[8192] = loss;
  else if (out_size == 1)    out[0]    = loss;
}

extern "C" void kernel_launch(void* const* d_in, const int* in_sizes, int n_in,
                              void* d_out, int out_size)
{
  const float* x      = (const float*)d_in[0];
  const float* labels = (const float*)d_in[1];
  const float* W0     = (const float*)d_in[2];
  const float* b0     = (const float*)d_in[3];
  const float* Wl     = (const float*)d_in[4];
  const float* bl     = (const float*)d_in[5];
  const float* Wd     = (const float*)d_in[6];
  const float* bd     = (const float*)d_in[7];
  float* out = (float*)d_out;

  cudaFuncSetAttribute(lstm_kernel, cudaFuncAttributeMaxDynamicSharedMemorySize, SMEM_DYN);

  init_kernel<<<16, 512>>>();
  lstm_kernel<<<128, 512, SMEM_DYN>>>(x, labels, W0, b0, Wl, bl, Wd, bd, out, out_size);
  finish_kernel<<<1, 1>>>(out, out_size);
}

// round 5
// speedup vs baseline: 3.9062x; 1.1840x over previous
#include <cuda_runtime.h>
#include <cuda_bf16.h>
#include <cstdint>

#define TT 64
#define AS 136   // A row stride (bf16 elems) -> 272 B
#define WS 264   // W row stride (bf16 elems) -> 528 B

// SMEM byte offsets
#define SM_BIAS 0                         // 256 f32
#define SM_LRED 1024                      // 64 f32
#define SM_A0   1536
#define A_PLANE 17408                     // 64 rows x AS bf16
#define SM_A(buf, plane) (SM_A0 + ((buf)*2 + (plane)) * A_PLANE)
#define SM_WH   (SM_A0 + 4*A_PLANE)       // 71168
#define SM_WL   (SM_WH + 128*WS*2)        // 138752
#define SMEM_DYN (SM_WL + 128*WS*2)       // 206336

// h exchange in consumer A-fragment layout: [t][half][plane][rb(4)][kk(4)][lane(32)] uint4
#define GFIDX(t,hf,pl,rb,kk) ((((((t)*2+(hf))*2+(pl))*4+(rb))*4)+(kk))
__device__ uint4 g_frag[64ull*2*2*4*4*32];
// flags: [(l*64+t)*2+half] for l<63, plus one loss-handshake flag at index 8064
#define FLAG_LOSS 8064
__device__ int g_flag[63*64*2 + 1];       // static zero-init; self-cleaning per run
__device__ float g_losspart0;

__device__ __forceinline__ uint32_t smem_to_u32(const void* p){
  uint32_t a; asm("{ .reg .u64 t; cvta.to.shared.u64 t, %1; cvt.u32.u64 %0, t; }" : "=r"(a) : "l"(p)); return a;
}
__device__ __forceinline__ float tanha(float x){
  float y; asm("tanh.approx.f32 %0, %1;" : "=f"(y) : "f"(x)); return y;
}
__device__ __forceinline__ float siga(float x){
  return fmaf(0.5f, tanha(0.5f * x), 0.5f);
}

#define LDSM_X4(r, a) asm volatile("ldmatrix.sync.aligned.m8n8.x4.shared.b16 {%0,%1,%2,%3}, [%4];" \
  : "=r"((r)[0]),"=r"((r)[1]),"=r"((r)[2]),"=r"((r)[3]) : "r"(a))
#define LDSM_X4T(r, a) asm volatile("ldmatrix.sync.aligned.m8n8.x4.trans.shared.b16 {%0,%1,%2,%3}, [%4];" \
  : "=r"((r)[0]),"=r"((r)[1]),"=r"((r)[2]),"=r"((r)[3]) : "r"(a))
#define MMA16816(d, a, b0v, b1v) asm volatile( \
  "mma.sync.aligned.m16n8k16.row.col.f32.bf16.bf16.f32 {%0,%1,%2,%3}, {%4,%5,%6,%7}, {%8,%9}, {%0,%1,%2,%3};" \
  : "+f"((d)[0]),"+f"((d)[1]),"+f"((d)[2]),"+f"((d)[3]) \
  : "r"((a)[0]),"r"((a)[1]),"r"((a)[2]),"r"((a)[3]), "r"(b0v),"r"(b1v))

// own-h slab: A from smem buf (LDSM), K rows 0..63 of W
__device__ __forceinline__ void own_gemm(const char* smem, uint32_t smb, int rdbuf,
                                         int mg, int qu, int ln, float acc[2][4][4]){
  const uint32_t arow  = (uint32_t)(mg * 32 + (ln & 15));
  const uint32_t acol8 = (uint32_t)((ln >> 4) << 3);
  const uint32_t bro   = (uint32_t)((ln & 15) + ((ln >> 4) << 4));
  #pragma unroll
  for (int kkp = 0; kkp < 2; kkp++){
    uint32_t AF[2][2][2][4];   // [kx][plane][mt][4]
    #pragma unroll
    for (int kx = 0; kx < 2; kx++){
      const int k0 = (kkp * 2 + kx) * 16;
      #pragma unroll
      for (int mt = 0; mt < 2; mt++){
        uint32_t ao = ((arow + mt * 16) * AS + k0 + acol8) * 2;
        LDSM_X4(AF[kx][0][mt], smb + SM_A(rdbuf, 0) + ao);
        LDSM_X4(AF[kx][1][mt], smb + SM_A(rdbuf, 1) + ao);
      }
    }
    #pragma unroll
    for (int g = 0; g < 4; g++){
      uint32_t bh[4], bl[4];
      const uint32_t bo = ((kkp * 32 + bro) * WS + g * 64 + qu * 8) * 2;
      LDSM_X4T(bh, smb + SM_WH + bo);
      LDSM_X4T(bl, smb + SM_WL + bo);
      #pragma unroll
      for (int mt = 0; mt < 2; mt++){
        MMA16816(acc[mt][g], AF[0][0][mt], bh[0], bh[1]);
        MMA16816(acc[mt][g], AF[0][1][mt], bh[0], bh[1]);
        MMA16816(acc[mt][g], AF[0][0][mt], bl[0], bl[1]);
        MMA16816(acc[mt][g], AF[1][0][mt], bh[2], bh[3]);
        MMA16816(acc[mt][g], AF[1][1][mt], bh[2], bh[3]);
        MMA16816(acc[mt][g], AF[1][0][mt], bl[2], bl[3]);
      }
    }
  }
}

// x slab (l>0): A-fragments straight from g_frag via LDG.128, K rows 64..127 of W
__device__ __forceinline__ void x_gemm(uint32_t smb, const uint4* __restrict__ fbase,
                                       int mg, int qu, int ln, float acc[2][4][4]){
  const uint32_t bro = (uint32_t)((ln & 15) + ((ln >> 4) << 4));
  #pragma unroll
  for (int kkp = 0; kkp < 2; kkp++){
    uint4 FH[2][2], FL[2][2];   // [kx][mt]
    #pragma unroll
    for (int kx = 0; kx < 2; kx++){
      const int kk = kkp * 2 + kx;
      #pragma unroll
      for (int mt = 0; mt < 2; mt++){
        const int rb = mg * 2 + mt;
        FH[kx][mt] = fbase[((0 * 4 + rb) * 4 + kk) * 32 + ln];
        FL[kx][mt] = fbase[((1 * 4 + rb) * 4 + kk) * 32 + ln];
      }
    }
    #pragma unroll
    for (int g = 0; g < 4; g++){
      uint32_t bh[4], bl[4];
      const uint32_t bo = ((64 + kkp * 32 + bro) * WS + g * 64 + qu * 8) * 2;
      LDSM_X4T(bh, smb + SM_WH + bo);
      LDSM_X4T(bl, smb + SM_WL + bo);
      #pragma unroll
      for (int mt = 0; mt < 2; mt++){
        MMA16816(acc[mt][g], ((uint32_t*)&FH[0][mt]), bh[0], bh[1]);
        MMA16816(acc[mt][g], ((uint32_t*)&FL[0][mt]), bh[0], bh[1]);
        MMA16816(acc[mt][g], ((uint32_t*)&FH[0][mt]), bl[0], bl[1]);
        MMA16816(acc[mt][g], ((uint32_t*)&FH[1][mt]), bh[2], bh[3]);
        MMA16816(acc[mt][g], ((uint32_t*)&FL[1][mt]), bh[2], bh[3]);
        MMA16816(acc[mt][g], ((uint32_t*)&FH[1][mt]), bl[2], bl[3]);
      }
    }
  }
}

// x slab for layer 0: input is x scalar at k-col 0 of the x slab; frags built in regs
__device__ __forceinline__ void x_gemm_l0(uint32_t smb, const float* __restrict__ x,
                                          int t, int half, int mg, int qu, int ln,
                                          float acc[2][4][4]){
  uint32_t fh[2][4] = {{0,0,0,0},{0,0,0,0}};
  uint32_t fl[2][4] = {{0,0,0,0},{0,0,0,0}};
  #pragma unroll
  for (int mt = 0; mt < 2; mt++){
    const int b0 = (mg * 2 + mt) * 16 + (ln >> 2);
    float xa = x[(size_t)(half * 64 + b0) * TT + t];
    float xb = x[(size_t)(half * 64 + b0 + 8) * TT + t];
    __nv_bfloat16 ha = __float2bfloat16_rn(xa), hb = __float2bfloat16_rn(xb);
    __nv_bfloat16 la = __float2bfloat16_rn(xa - __bfloat162float(ha));
    __nv_bfloat16 lb = __float2bfloat16_rn(xb - __bfloat162float(hb));
    if ((ln & 3) == 0){
      fh[mt][0] = (uint32_t)__bfloat16_as_ushort(ha);
      fh[mt][1] = (uint32_t)__bfloat16_as_ushort(hb);
      fl[mt][0] = (uint32_t)__bfloat16_as_ushort(la);
      fl[mt][1] = (uint32_t)__bfloat16_as_ushort(lb);
    }
  }
  const uint32_t bro = (uint32_t)((ln & 15) + ((ln >> 4) << 4));
  #pragma unroll
  for (int g = 0; g < 4; g++){
    uint32_t bh[4], bl[4];
    const uint32_t bo = ((64 + bro) * WS + g * 64 + qu * 8) * 2;   // kkp=0 only
    LDSM_X4T(bh, smb + SM_WH + bo);
    LDSM_X4T(bl, smb + SM_WL + bo);
    #pragma unroll
    for (int mt = 0; mt < 2; mt++){
      MMA16816(acc[mt][g], fh[mt], bh[0], bh[1]);
      MMA16816(acc[mt][g], fl[mt], bh[0], bh[1]);
      MMA16816(acc[mt][g], fh[mt], bl[0], bl[1]);
    }
  }
}

__global__ __launch_bounds__(512, 1)
void lstm_kernel(const float* __restrict__ x, const float* __restrict__ labels,
                 const float* __restrict__ W0, const float* __restrict__ b0,
                 const float* __restrict__ Wl, const float* __restrict__ bl,
                 const float* __restrict__ Wd, const float* __restrict__ bd,
                 float* __restrict__ out, int out_size)
{
  extern __shared__ char smem[];
  const uint32_t smb = smem_to_u32(smem);
  float* biasS = (float*)(smem + SM_BIAS);
  float* lred  = (float*)(smem + SM_LRED);

  const int l    = blockIdx.x >> 1;
  const int half = blockIdx.x & 1;
  const int tid  = threadIdx.x;
  const int w    = tid >> 5;
  const int ln   = tid & 31;
  const int mg   = w & 1;
  const int qu   = w >> 1;
  const int tq   = ln >> 2, tr = ln & 3;
  const int u0   = qu * 8 + tr * 2;

  // ---- build split weights (k: [own h 0..63 | lower/x 64..127]) ----
  for (int idx = tid; idx < 32768; idx += 512){
    int k = idx >> 8, n = idx & 255;
    float wv;
    if (l == 0) wv = (k < 64) ? W0[(1 + k) * 256 + n] : (k == 64 ? W0[n] : 0.0f);
    else {
      const float* Wsrc = Wl + (size_t)(l - 1) * 32768;
      wv = (k < 64) ? Wsrc[(64 + k) * 256 + n] : Wsrc[(k - 64) * 256 + n];
    }
    __nv_bfloat16 bh  = __float2bfloat16_rn(wv);
    __nv_bfloat16 bl2 = __float2bfloat16_rn(wv - __bfloat162float(bh));
    *(__nv_bfloat16*)(smem + SM_WH + ((size_t)k * WS + n) * 2) = bh;
    *(__nv_bfloat16*)(smem + SM_WL + ((size_t)k * WS + n) * 2) = bl2;
  }
  {
    const float* bs = (l == 0) ? b0 : bl + (size_t)(l - 1) * 256;
    for (int i = tid; i < 256; i += 512) biasS[i] = bs[i];
  }
  for (int i = tid; i < 4 * A_PLANE / 4; i += 512)
    ((uint32_t*)(smem + SM_A0))[i] = 0u;
  __syncthreads();

  float bsr[4][2];
  #pragma unroll
  for (int g = 0; g < 4; g++)
    #pragma unroll
    for (int j = 0; j < 2; j++) bsr[g][j] = biasS[g * 64 + u0 + j];

  float cst[8];
  #pragma unroll
  for (int i = 0; i < 8; i++) cst[i] = 0.0f;
  float lsum = 0.0f;

  // producer fragment-store constants
  const int p_kk   = qu >> 1;
  const int p_lane = tq * 4 + tr;
  const int p_rg   = (qu & 1) * 2;   // + rh

  for (int t = 0; t < TT; t++){
    float acc[2][4][4];
    #pragma unroll
    for (int mt = 0; mt < 2; mt++)
      #pragma unroll
      for (int g = 0; g < 4; g++)
        #pragma unroll
        for (int ci = 0; ci < 4; ci++) acc[mt][g][ci] = 0.0f;

    // 1. own-h GEMM from smem buf (t&1)
    own_gemm(smem, smb, t & 1, mg, qu, ln, acc);

    // 2+3. acquire lower h, x-slab GEMM (fragments straight from global)
    if (l > 0){
      const int* fp = &g_flag[((l - 1) * 64 + t) * 2 + half];
      unsigned v;
      do { asm volatile("ld.acquire.gpu.b32 %0, [%1];" : "=r"(v) : "l"(fp) : "memory"); } while (v == 0u);
      const uint4* fbase = &g_frag[(size_t)GFIDX(t, half, 0, 0, 0) * 32];
      x_gemm(smb, fbase, mg, qu, ln, acc);
    } else {
      x_gemm_l0(smb, x, t, half, mg, qu, ln, acc);
    }

    // 4. epilogue: gates -> c, h
    float hv[8];
    #pragma unroll
    for (int mt = 0; mt < 2; mt++)
      #pragma unroll
      for (int ci = 0; ci < 4; ci++){
        const int j = ci & 1;
        const int ii = mt * 4 + ci;
        float vi = acc[mt][0][ci] + bsr[0][j];
        float vj = acc[mt][1][ci] + bsr[1][j];
        float vf = acc[mt][2][ci] + bsr[2][j];
        float vo = acc[mt][3][ci] + bsr[3][j];
        float cc = cst[ii] * siga(vf) + siga(vi) * tanha(vj);
        cst[ii] = cc;
        hv[ii] = tanha(cc) * siga(vo);
      }

    // 5. store h: smem buf (t+1)&1 for own-GEMM + g_frag scatter for upper layer
    const int wb = (t + 1) & 1;
    #pragma unroll
    for (int mt = 0; mt < 2; mt++)
      #pragma unroll
      for (int rh = 0; rh < 2; rh++){
        const int b  = mg * 32 + mt * 16 + tq + rh * 8;
        const int i0 = mt * 4 + rh * 2;
        float h0 = hv[i0], h1 = hv[i0 + 1];
        __nv_bfloat16 a0 = __float2bfloat16_rn(h0);
        __nv_bfloat16 a1 = __float2bfloat16_rn(h1);
        __nv_bfloat16 l0 = __float2bfloat16_rn(h0 - __bfloat162float(a0));
        __nv_bfloat16 l1 = __float2bfloat16_rn(h1 - __bfloat162float(a1));
        uint32_t hi0 = __bfloat16_as_ushort(a0), hi1 = __bfloat16_as_ushort(a1);
        uint32_t lo0 = __bfloat16_as_ushort(l0), lo1 = __bfloat16_as_ushort(l1);
        const uint32_t wh = hi0 | (hi1 << 16);
        const uint32_t wl = lo0 | (lo1 << 16);
        *(uint32_t*)(smem + SM_A(wb, 0) + (b * AS + u0) * 2) = wh;
        *(uint32_t*)(smem + SM_A(wb, 1) + (b * AS + u0) * 2) = wl;
        if (l < 63){
          const int rb = mg * 2 + mt;
          uint32_t* wp0 = (uint32_t*)&g_frag[(size_t)GFIDX(t, half, 0, rb, p_kk) * 32 + p_lane];
          uint32_t* wp1 = (uint32_t*)&g_frag[(size_t)GFIDX(t, half, 1, rb, p_kk) * 32 + p_lane];
          wp0[p_rg + rh] = wh;
          wp1[p_rg + rh] = wl;
        }
      }

    __syncthreads();   // orders: h smem stores (next own-GEMM), g_frag stores (release), poll passes (flag reset)

    if (tid == 0){
      if (l > 0){      // reset consumed flag (self-cleaning for graph replays)
        int* cp = &g_flag[((l - 1) * 64 + t) * 2 + half];
        asm volatile("st.relaxed.gpu.b32 [%0], %1;" :: "l"(cp), "r"(0) : "memory");
      }
      if (l < 63){     // publish h(t): bar.sync + release gives cumulative ordering
        int* fp = &g_flag[(l * 64 + t) * 2 + half];
        asm volatile("st.release.gpu.b32 [%0], %1;" :: "l"(fp), "r"(1) : "memory");
      }
    }

    if (l == 63 && tid < 64){
      // fused dense(1) + relu + loss partial
      const int r = tid;
      float accd = bd[t];
      const uint32_t* hp = (const uint32_t*)(smem + SM_A(wb, 0) + r * AS * 2);
      const uint32_t* lp = (const uint32_t*)(smem + SM_A(wb, 1) + r * AS * 2);
      const float* wd = &Wd[(size_t)t * 64];
      #pragma unroll 8
      for (int i2 = 0; i2 < 32; i2++){
        uint32_t hh = hp[i2], lv = lp[i2];
        float h0 = __bfloat162float(__ushort_as_bfloat16((unsigned short)(hh & 0xFFFF)))
                 + __bfloat162float(__ushort_as_bfloat16((unsigned short)(lv & 0xFFFF)));
        float h1 = __bfloat162float(__ushort_as_bfloat16((unsigned short)(hh >> 16)))
                 + __bfloat162float(__ushort_as_bfloat16((unsigned short)(lv >> 16)));
        accd += h0 * wd[2 * i2] + h1 * wd[2 * i2 + 1];
      }
      float pred = fmaxf(accd, 0.0f);
      const int gb = half * 64 + r;
      if (out_size >= 8192) out[(size_t)gb * TT + t] = pred;
      float d = labels[(size_t)gb * TT + t] - pred;
      lsum += d * d;
    }
  }

  // loss: (63,0) -> (63,1) handshake, deterministic fixed-order sums
  if (l == 63){
    if (tid < 64) lred[tid] = lsum;
    __syncthreads();
    if (tid == 0){
      float s = 0.0f;
      for (int i = 0; i < 64; i++) s += lred[i];
      int* lf = &g_flag[FLAG_LOSS];
      if (half == 0){
        g_losspart0 = s;
        asm volatile("st.release.gpu.b32 [%0], %1;" :: "l"(lf), "r"(1) : "memory");
      } else {
        unsigned v;
        do { asm volatile("ld.acquire.gpu.b32 %0, [%1];" : "=r"(v) : "l"(lf) : "memory"); } while (v == 0u);
        float loss = (g_losspart0 + s) * (1.0f / 8192.0f);
        if (out_size >= 8193)   out[8192] = loss;
        else if (out_size == 1) out[0]   = loss;
        asm volatile("st.relaxed.gpu.b32 [%0], %1;" :: "l"(lf), "r"(0) : "memory");
      }
    }
  }
}

extern "C" void kernel_launch(void* const* d_in, const int* in_sizes, int n_in,
                              void* d_out, int out_size)
{
  const float* x      = (const float*)d_in[0];
  const float* labels = (const float*)d_in[1];
  const float* W0     = (const float*)d_in[2];
  const float* b0     = (const float*)d_in[3];
  const float* Wl     = (const float*)d_in[4];
  const float* bl     = (const float*)d_in[5];
  const float* Wd     = (const float*)d_in[6];
  const float* bd     = (const float*)d_in[7];
  float* out = (float*)d_out;

  cudaFuncSetAttribute(lstm_kernel, cudaFuncAttributeMaxDynamicSharedMemorySize, SMEM_DYN);
  lstm_kernel<<<128, 512, SMEM_DYN>>>(x, labels, W0, b0, Wl, bl, Wd, bd, out, out_size);
}

// round 6
// speedup vs baseline: 4.8475x; 1.2410x over previous
#include <cuda_runtime.h>
#include <cuda_bf16.h>
#include <cstdint>

#define TT 64
#define AS 136   // A row stride (bf16 elems) -> 272 B
#define WS 264   // W row stride (bf16 elems) -> 528 B

// SMEM byte offsets
#define SM_BIAS 0                         // 256 f32
#define SM_LRED 1024                      // 64 f32
#define SM_A0   1536
#define A_PLANE 17408                     // 64 rows x AS bf16
#define SM_A(buf, plane) (SM_A0 + ((buf)*2 + (plane)) * A_PLANE)
#define SM_WH   (SM_A0 + 4*A_PLANE)       // 71168
#define SMEM_DYN (SM_WH + 128*WS*2)       // 138752

// h exchange in consumer A-fragment layout: [t][half][plane][rb(4)][kk(4)][lane(32)] uint4
#define GFIDX(t,hf,pl,rb,kk) ((((((t)*2+(hf))*2+(pl))*4+(rb))*4)+(kk))
__device__ uint4 g_frag[64ull*2*2*4*4*32];
// flags: [(l*64+t)*2+half] for l<63, plus one loss-handshake flag at index 8064
#define FLAG_LOSS 8064
__device__ int g_flag[63*64*2 + 1];       // static zero-init; self-cleaning per run
__device__ float g_losspart0;

__device__ __forceinline__ uint32_t smem_to_u32(const void* p){
  uint32_t a; asm("{ .reg .u64 t; cvta.to.shared.u64 t, %1; cvt.u32.u64 %0, t; }" : "=r"(a) : "l"(p)); return a;
}
__device__ __forceinline__ float tanha(float x){
  float y; asm("tanh.approx.f32 %0, %1;" : "=f"(y) : "f"(x)); return y;
}
__device__ __forceinline__ float siga(float x){
  return fmaf(0.5f, tanha(0.5f * x), 0.5f);
}

#define LDSM_X4(r, a) asm volatile("ldmatrix.sync.aligned.m8n8.x4.shared.b16 {%0,%1,%2,%3}, [%4];" \
  : "=r"((r)[0]),"=r"((r)[1]),"=r"((r)[2]),"=r"((r)[3]) : "r"(a))
#define LDSM_X4T(r, a) asm volatile("ldmatrix.sync.aligned.m8n8.x4.trans.shared.b16 {%0,%1,%2,%3}, [%4];" \
  : "=r"((r)[0]),"=r"((r)[1]),"=r"((r)[2]),"=r"((r)[3]) : "r"(a))
#define MMA16816(d, a, b0v, b1v) asm volatile( \
  "mma.sync.aligned.m16n8k16.row.col.f32.bf16.bf16.f32 {%0,%1,%2,%3}, {%4,%5,%6,%7}, {%8,%9}, {%0,%1,%2,%3};" \
  : "+f"((d)[0]),"+f"((d)[1]),"+f"((d)[2]),"+f"((d)[3]) \
  : "r"((a)[0]),"r"((a)[1]),"r"((a)[2]),"r"((a)[3]), "r"(b0v),"r"(b1v))

// own-h slab: A (hi+lo planes) from smem buf (LDSM) x W-hi, K rows 0..63
__device__ __forceinline__ void own_gemm(const char* smem, uint32_t smb, int rdbuf,
                                         int mg, int qu, int ln, float acc[2][4][4]){
  const uint32_t arow  = (uint32_t)(mg * 32 + (ln & 15));
  const uint32_t acol8 = (uint32_t)((ln >> 4) << 3);
  const uint32_t bro   = (uint32_t)((ln & 15) + ((ln >> 4) << 4));
  #pragma unroll
  for (int kkp = 0; kkp < 2; kkp++){
    uint32_t AF[2][2][2][4];   // [kx][plane][mt][4]
    #pragma unroll
    for (int kx = 0; kx < 2; kx++){
      const int k0 = (kkp * 2 + kx) * 16;
      #pragma unroll
      for (int mt = 0; mt < 2; mt++){
        uint32_t ao = ((arow + mt * 16) * AS + k0 + acol8) * 2;
        LDSM_X4(AF[kx][0][mt], smb + SM_A(rdbuf, 0) + ao);
        LDSM_X4(AF[kx][1][mt], smb + SM_A(rdbuf, 1) + ao);
      }
    }
    #pragma unroll
    for (int g = 0; g < 4; g++){
      uint32_t bh[4];
      const uint32_t bo = ((kkp * 32 + bro) * WS + g * 64 + qu * 8) * 2;
      LDSM_X4T(bh, smb + SM_WH + bo);
      #pragma unroll
      for (int mt = 0; mt < 2; mt++){
        MMA16816(acc[mt][g], AF[0][0][mt], bh[0], bh[1]);
        MMA16816(acc[mt][g], AF[0][1][mt], bh[0], bh[1]);
        MMA16816(acc[mt][g], AF[1][0][mt], bh[2], bh[3]);
        MMA16816(acc[mt][g], AF[1][1][mt], bh[2], bh[3]);
      }
    }
  }
}

// x slab (l>0): A-fragments (hi+lo) straight from g_frag via LDG.128 x W-hi, K rows 64..127
__device__ __forceinline__ void x_gemm(uint32_t smb, const uint4* __restrict__ fbase,
                                       int mg, int qu, int ln, float acc[2][4][4]){
  const uint32_t bro = (uint32_t)((ln & 15) + ((ln >> 4) << 4));
  #pragma unroll
  for (int kkp = 0; kkp < 2; kkp++){
    uint4 FH[2][2], FL[2][2];   // [kx][mt]
    #pragma unroll
    for (int kx = 0; kx < 2; kx++){
      const int kk = kkp * 2 + kx;
      #pragma unroll
      for (int mt = 0; mt < 2; mt++){
        const int rb = mg * 2 + mt;
        FH[kx][mt] = fbase[((0 * 4 + rb) * 4 + kk) * 32 + ln];
        FL[kx][mt] = fbase[((1 * 4 + rb) * 4 + kk) * 32 + ln];
      }
    }
    #pragma unroll
    for (int g = 0; g < 4; g++){
      uint32_t bh[4];
      const uint32_t bo = ((64 + kkp * 32 + bro) * WS + g * 64 + qu * 8) * 2;
      LDSM_X4T(bh, smb + SM_WH + bo);
      #pragma unroll
      for (int mt = 0; mt < 2; mt++){
        MMA16816(acc[mt][g], ((uint32_t*)&FH[0][mt]), bh[0], bh[1]);
        MMA16816(acc[mt][g], ((uint32_t*)&FL[0][mt]), bh[0], bh[1]);
        MMA16816(acc[mt][g], ((uint32_t*)&FH[1][mt]), bh[2], bh[3]);
        MMA16816(acc[mt][g], ((uint32_t*)&FL[1][mt]), bh[2], bh[3]);
      }
    }
  }
}

// x slab for layer 0: input is x scalar at k-col 0 of the x slab; frags built in regs
__device__ __forceinline__ void x_gemm_l0(uint32_t smb, const float* __restrict__ x,
                                          int t, int half, int mg, int qu, int ln,
                                          float acc[2][4][4]){
  uint32_t fh[2][4] = {{0,0,0,0},{0,0,0,0}};
  uint32_t fl[2][4] = {{0,0,0,0},{0,0,0,0}};
  #pragma unroll
  for (int mt = 0; mt < 2; mt++){
    const int b0 = (mg * 2 + mt) * 16 + (ln >> 2);
    float xa = x[(size_t)(half * 64 + b0) * TT + t];
    float xb = x[(size_t)(half * 64 + b0 + 8) * TT + t];
    __nv_bfloat16 ha = __float2bfloat16_rn(xa), hb = __float2bfloat16_rn(xb);
    __nv_bfloat16 la = __float2bfloat16_rn(xa - __bfloat162float(ha));
    __nv_bfloat16 lb = __float2bfloat16_rn(xb - __bfloat162float(hb));
    if ((ln & 3) == 0){
      fh[mt][0] = (uint32_t)__bfloat16_as_ushort(ha);
      fh[mt][1] = (uint32_t)__bfloat16_as_ushort(hb);
      fl[mt][0] = (uint32_t)__bfloat16_as_ushort(la);
      fl[mt][1] = (uint32_t)__bfloat16_as_ushort(lb);
    }
  }
  const uint32_t bro = (uint32_t)((ln & 15) + ((ln >> 4) << 4));
  #pragma unroll
  for (int g = 0; g < 4; g++){
    uint32_t bh[4];
    const uint32_t bo = ((64 + bro) * WS + g * 64 + qu * 8) * 2;   // kkp=0 only
    LDSM_X4T(bh, smb + SM_WH + bo);
    #pragma unroll
    for (int mt = 0; mt < 2; mt++){
      MMA16816(acc[mt][g], fh[mt], bh[0], bh[1]);
      MMA16816(acc[mt][g], fl[mt], bh[0], bh[1]);
    }
  }
}

__global__ __launch_bounds__(512, 1)
void lstm_kernel(const float* __restrict__ x, const float* __restrict__ labels,
                 const float* __restrict__ W0, const float* __restrict__ b0,
                 const float* __restrict__ Wl, const float* __restrict__ bl,
                 const float* __restrict__ Wd, const float* __restrict__ bd,
                 float* __restrict__ out, int out_size)
{
  extern __shared__ char smem[];
  const uint32_t smb = smem_to_u32(smem);
  float* biasS = (float*)(smem + SM_BIAS);
  float* lred  = (float*)(smem + SM_LRED);

  const int l    = blockIdx.x >> 1;
  const int half = blockIdx.x & 1;
  const int tid  = threadIdx.x;
  const int w    = tid >> 5;
  const int ln   = tid & 31;
  const int mg   = w & 1;
  const int qu   = w >> 1;
  const int tq   = ln >> 2, tr = ln & 3;
  const int u0   = qu * 8 + tr * 2;

  // ---- build bf16 weights (k: [own h 0..63 | lower/x 64..127]) ----
  for (int idx = tid; idx < 32768; idx += 512){
    int k = idx >> 8, n = idx & 255;
    float wv;
    if (l == 0) wv = (k < 64) ? W0[(1 + k) * 256 + n] : (k == 64 ? W0[n] : 0.0f);
    else {
      const float* Wsrc = Wl + (size_t)(l - 1) * 32768;
      wv = (k < 64) ? Wsrc[(64 + k) * 256 + n] : Wsrc[(k - 64) * 256 + n];
    }
    *(__nv_bfloat16*)(smem + SM_WH + ((size_t)k * WS + n) * 2) = __float2bfloat16_rn(wv);
  }
  {
    const float* bs = (l == 0) ? b0 : bl + (size_t)(l - 1) * 256;
    for (int i = tid; i < 256; i += 512) biasS[i] = bs[i];
  }
  for (int i = tid; i < 4 * A_PLANE / 4; i += 512)
    ((uint32_t*)(smem + SM_A0))[i] = 0u;
  __syncthreads();

  float bsr[4][2];
  #pragma unroll
  for (int g = 0; g < 4; g++)
    #pragma unroll
    for (int j = 0; j < 2; j++) bsr[g][j] = biasS[g * 64 + u0 + j];

  float cst[8];
  #pragma unroll
  for (int i = 0; i < 8; i++) cst[i] = 0.0f;
  float lsum = 0.0f;

  // producer fragment-store constants
  const int p_kk   = qu >> 1;
  const int p_lane = tq * 4 + tr;
  const int p_rg   = (qu & 1) * 2;   // + rh

  for (int t = 0; t < TT; t++){
    float acc[2][4][4];
    #pragma unroll
    for (int mt = 0; mt < 2; mt++)
      #pragma unroll
      for (int g = 0; g < 4; g++)
        #pragma unroll
        for (int ci = 0; ci < 4; ci++) acc[mt][g][ci] = 0.0f;

    // 1. own-h GEMM from smem buf (t&1)
    own_gemm(smem, smb, t & 1, mg, qu, ln, acc);

    // 2+3. acquire lower h, x-slab GEMM (fragments straight from global)
    if (l > 0){
      const int* fp = &g_flag[((l - 1) * 64 + t) * 2 + half];
      unsigned v;
      do { asm volatile("ld.acquire.gpu.b32 %0, [%1];" : "=r"(v) : "l"(fp) : "memory"); } while (v == 0u);
      const uint4* fbase = &g_frag[(size_t)GFIDX(t, half, 0, 0, 0) * 32];
      x_gemm(smb, fbase, mg, qu, ln, acc);
    } else {
      x_gemm_l0(smb, x, t, half, mg, qu, ln, acc);
    }

    // 4. epilogue: gates -> c, h
    float hv[8];
    #pragma unroll
    for (int mt = 0; mt < 2; mt++)
      #pragma unroll
      for (int ci = 0; ci < 4; ci++){
        const int j = ci & 1;
        const int ii = mt * 4 + ci;
        float vi = acc[mt][0][ci] + bsr[0][j];
        float vj = acc[mt][1][ci] + bsr[1][j];
        float vf = acc[mt][2][ci] + bsr[2][j];
        float vo = acc[mt][3][ci] + bsr[3][j];
        float cc = cst[ii] * siga(vf) + siga(vi) * tanha(vj);
        cst[ii] = cc;
        hv[ii] = tanha(cc) * siga(vo);
      }

    // 5. store h: smem buf (t+1)&1 for own-GEMM + g_frag scatter for upper layer
    const int wb = (t + 1) & 1;
    #pragma unroll
    for (int mt = 0; mt < 2; mt++)
      #pragma unroll
      for (int rh = 0; rh < 2; rh++){
        const int b  = mg * 32 + mt * 16 + tq + rh * 8;
        const int i0 = mt * 4 + rh * 2;
        float h0 = hv[i0], h1 = hv[i0 + 1];
        __nv_bfloat16 a0 = __float2bfloat16_rn(h0);
        __nv_bfloat16 a1 = __float2bfloat16_rn(h1);
        __nv_bfloat16 l0 = __float2bfloat16_rn(h0 - __bfloat162float(a0));
        __nv_bfloat16 l1 = __float2bfloat16_rn(h1 - __bfloat162float(a1));
        uint32_t hi0 = __bfloat16_as_ushort(a0), hi1 = __bfloat16_as_ushort(a1);
        uint32_t lo0 = __bfloat16_as_ushort(l0), lo1 = __bfloat16_as_ushort(l1);
        const uint32_t wh = hi0 | (hi1 << 16);
        const uint32_t wl = lo0 | (lo1 << 16);
        *(uint32_t*)(smem + SM_A(wb, 0) + (b * AS + u0) * 2) = wh;
        *(uint32_t*)(smem + SM_A(wb, 1) + (b * AS + u0) * 2) = wl;
        if (l < 63){
          const int rb = mg * 2 + mt;
          uint32_t* wp0 = (uint32_t*)&g_frag[(size_t)GFIDX(t, half, 0, rb, p_kk) * 32 + p_lane];
          uint32_t* wp1 = (uint32_t*)&g_frag[(size_t)GFIDX(t, half, 1, rb, p_kk) * 32 + p_lane];
          wp0[p_rg + rh] = wh;
          wp1[p_rg + rh] = wl;
        }
      }

    __syncthreads();   // orders: h smem stores (next own-GEMM), g_frag stores (release), poll passes (flag reset)

    if (tid == 0){
      if (l > 0){      // reset consumed flag (self-cleaning for graph replays)
        int* cp = &g_flag[((l - 1) * 64 + t) * 2 + half];
        asm volatile("st.relaxed.gpu.b32 [%0], %1;" :: "l"(cp), "r"(0) : "memory");
      }
      if (l < 63){     // publish h(t): bar.sync + release gives cumulative ordering
        int* fp = &g_flag[(l * 64 + t) * 2 + half];
        asm volatile("st.release.gpu.b32 [%0], %1;" :: "l"(fp), "r"(1) : "memory");
      }
    }

    if (l == 63 && tid < 64){
      // fused dense(1) + relu + loss partial
      const int r = tid;
      float accd = bd[t];
      const uint32_t* hp = (const uint32_t*)(smem + SM_A(wb, 0) + r * AS * 2);
      const uint32_t* lp = (const uint32_t*)(smem + SM_A(wb, 1) + r * AS * 2);
      const float* wd = &Wd[(size_t)t * 64];
      #pragma unroll 8
      for (int i2 = 0; i2 < 32; i2++){
        uint32_t hh = hp[i2], lv = lp[i2];
        float h0 = __bfloat162float(__ushort_as_bfloat16((unsigned short)(hh & 0xFFFF)))
                 + __bfloat162float(__ushort_as_bfloat16((unsigned short)(lv & 0xFFFF)));
        float h1 = __bfloat162float(__ushort_as_bfloat16((unsigned short)(hh >> 16)))
                 + __bfloat162float(__ushort_as_bfloat16((unsigned short)(lv >> 16)));
        accd += h0 * wd[2 * i2] + h1 * wd[2 * i2 + 1];
      }
      float pred = fmaxf(accd, 0.0f);
      const int gb = half * 64 + r;
      if (out_size >= 8192) out[(size_t)gb * TT + t] = pred;
      float d = labels[(size_t)gb * TT + t] - pred;
      lsum += d * d;
    }
  }

  // loss: (63,0) -> (63,1) handshake, deterministic fixed-order sums
  if (l == 63){
    if (tid < 64) lred[tid] = lsum;
    __syncthreads();
    if (tid == 0){
      float s = 0.0f;
      for (int i = 0; i < 64; i++) s += lred[i];
      int* lf = &g_flag[FLAG_LOSS];
      if (half == 0){
        g_losspart0 = s;
        asm volatile("st.release.gpu.b32 [%0], %1;" :: "l"(lf), "r"(1) : "memory");
      } else {
        unsigned v;
        do { asm volatile("ld.acquire.gpu.b32 %0, [%1];" : "=r"(v) : "l"(lf) : "memory"); } while (v == 0u);
        float loss = (g_losspart0 + s) * (1.0f / 8192.0f);
        if (out_size >= 8193)   out[8192] = loss;
        else if (out_size == 1) out[0]   = loss;
        asm volatile("st.relaxed.gpu.b32 [%0], %1;" :: "l"(lf), "r"(0) : "memory");
      }
    }
  }
}

extern "C" void kernel_launch(void* const* d_in, const int* in_sizes, int n_in,
                              void* d_out, int out_size)
{
  const float* x      = (const float*)d_in[0];
  const float* labels = (const float*)d_in[1];
  const float* W0     = (const float*)d_in[2];
  const float* b0     = (const float*)d_in[3];
  const float* Wl     = (const float*)d_in[4];
  const float* bl     = (const float*)d_in[5];
  const float* Wd     = (const float*)d_in[6];
  const float* bd     = (const float*)d_in[7];
  float* out = (float*)d_out;

  cudaFuncSetAttribute(lstm_kernel, cudaFuncAttributeMaxDynamicSharedMemorySize, SMEM_DYN);
  lstm_kernel<<<128, 512, SMEM_DYN>>>(x, labels, W0, b0, Wl, bl, Wd, bd, out, out_size);
}

// round 7
// speedup vs baseline: 6.4627x; 1.3332x over previous
#include <cuda_runtime.h>
#include <cuda_bf16.h>
#include <cstdint>

#define TT 64
#define AS 136   // A row stride (bf16 elems) -> 272 B
#define WS 264   // W row stride (bf16 elems) -> 528 B

// SMEM byte offsets
#define SM_BIAS 0                         // 256 f32
#define SM_LRED 1024                      // 64 f32
#define SM_A0   1536
#define A_PLANE 17408                     // 64 rows x AS bf16
#define SM_A(buf) (SM_A0 + (buf) * A_PLANE)
#define SM_WH   (SM_A0 + 2*A_PLANE)       // 36352
#define SMEM_DYN (SM_WH + 128*WS*2)       // 103936

// h exchange in consumer A-fragment layout: [t][half][rb(4)][kk(4)][lane(32)] uint4 (bf16 h, single plane)
#define GFIDX(t,hf,rb,kk) (((((t)*2+(hf))*4+(rb))*4)+(kk))
__device__ uint4 g_frag[64ull*2*4*4*32];
// flags: [(l*64+t)*2+half] for l<63, plus one loss-handshake flag at index 8064
#define FLAG_LOSS 8064
__device__ int g_flag[63*64*2 + 1];       // static zero-init; self-cleaning per run
__device__ float g_losspart0;

__device__ __forceinline__ uint32_t smem_to_u32(const void* p){
  uint32_t a; asm("{ .reg .u64 t; cvta.to.shared.u64 t, %1; cvt.u32.u64 %0, t; }" : "=r"(a) : "l"(p)); return a;
}
__device__ __forceinline__ float tanha(float x){
  float y; asm("tanh.approx.f32 %0, %1;" : "=f"(y) : "f"(x)); return y;
}
__device__ __forceinline__ float siga(float x){
  return fmaf(0.5f, tanha(0.5f * x), 0.5f);
}

#define LDSM_X4(r, a) asm volatile("ldmatrix.sync.aligned.m8n8.x4.shared.b16 {%0,%1,%2,%3}, [%4];" \
  : "=r"((r)[0]),"=r"((r)[1]),"=r"((r)[2]),"=r"((r)[3]) : "r"(a))
#define LDSM_X4T(r, a) asm volatile("ldmatrix.sync.aligned.m8n8.x4.trans.shared.b16 {%0,%1,%2,%3}, [%4];" \
  : "=r"((r)[0]),"=r"((r)[1]),"=r"((r)[2]),"=r"((r)[3]) : "r"(a))
#define MMA16816(d, a, b0v, b1v) asm volatile( \
  "mma.sync.aligned.m16n8k16.row.col.f32.bf16.bf16.f32 {%0,%1,%2,%3}, {%4,%5,%6,%7}, {%8,%9}, {%0,%1,%2,%3};" \
  : "+f"((d)[0]),"+f"((d)[1]),"+f"((d)[2]),"+f"((d)[3]) \
  : "r"((a)[0]),"r"((a)[1]),"r"((a)[2]),"r"((a)[3]), "r"(b0v),"r"(b1v))

// own-h slab: A (bf16, single plane) from smem buf (LDSM) x W, K rows 0..63
__device__ __forceinline__ void own_gemm(const char* smem, uint32_t smb, int rdbuf,
                                         int mg, int qu, int ln, float acc[2][4][4]){
  const uint32_t arow  = (uint32_t)(mg * 32 + (ln & 15));
  const uint32_t acol8 = (uint32_t)((ln >> 4) << 3);
  const uint32_t bro   = (uint32_t)((ln & 15) + ((ln >> 4) << 4));
  #pragma unroll
  for (int kkp = 0; kkp < 2; kkp++){
    uint32_t AF[2][2][4];   // [kx][mt][4]
    #pragma unroll
    for (int kx = 0; kx < 2; kx++){
      const int k0 = (kkp * 2 + kx) * 16;
      #pragma unroll
      for (int mt = 0; mt < 2; mt++){
        uint32_t ao = ((arow + mt * 16) * AS + k0 + acol8) * 2;
        LDSM_X4(AF[kx][mt], smb + SM_A(rdbuf) + ao);
      }
    }
    #pragma unroll
    for (int g = 0; g < 4; g++){
      uint32_t bh[4];
      const uint32_t bo = ((kkp * 32 + bro) * WS + g * 64 + qu * 8) * 2;
      LDSM_X4T(bh, smb + SM_WH + bo);
      #pragma unroll
      for (int mt = 0; mt < 2; mt++){
        MMA16816(acc[mt][g], AF[0][mt], bh[0], bh[1]);
        MMA16816(acc[mt][g], AF[1][mt], bh[2], bh[3]);
      }
    }
  }
}

// x slab (l>0): A-fragments straight from g_frag via LDG.128 x W, K rows 64..127
__device__ __forceinline__ void x_gemm(uint32_t smb, const uint4* __restrict__ fbase,
                                       int mg, int qu, int ln, float acc[2][4][4]){
  const uint32_t bro = (uint32_t)((ln & 15) + ((ln >> 4) << 4));
  #pragma unroll
  for (int kkp = 0; kkp < 2; kkp++){
    uint4 FH[2][2];   // [kx][mt]
    #pragma unroll
    for (int kx = 0; kx < 2; kx++){
      const int kk = kkp * 2 + kx;
      #pragma unroll
      for (int mt = 0; mt < 2; mt++){
        const int rb = mg * 2 + mt;
        FH[kx][mt] = fbase[(rb * 4 + kk) * 32 + ln];
      }
    }
    #pragma unroll
    for (int g = 0; g < 4; g++){
      uint32_t bh[4];
      const uint32_t bo = ((64 + kkp * 32 + bro) * WS + g * 64 + qu * 8) * 2;
      LDSM_X4T(bh, smb + SM_WH + bo);
      #pragma unroll
      for (int mt = 0; mt < 2; mt++){
        MMA16816(acc[mt][g], ((uint32_t*)&FH[0][mt]), bh[0], bh[1]);
        MMA16816(acc[mt][g], ((uint32_t*)&FH[1][mt]), bh[2], bh[3]);
      }
    }
  }
}

// x slab for layer 0: x scalar split hi+lo (cheap here: only 2 frag regs, kkp=0 only)
__device__ __forceinline__ void x_gemm_l0(uint32_t smb, const float* __restrict__ x,
                                          int t, int half, int mg, int qu, int ln,
                                          float acc[2][4][4]){
  uint32_t fh[2][4] = {{0,0,0,0},{0,0,0,0}};
  uint32_t fl[2][4] = {{0,0,0,0},{0,0,0,0}};
  #pragma unroll
  for (int mt = 0; mt < 2; mt++){
    const int b0 = (mg * 2 + mt) * 16 + (ln >> 2);
    float xa = x[(size_t)(half * 64 + b0) * TT + t];
    float xb = x[(size_t)(half * 64 + b0 + 8) * TT + t];
    __nv_bfloat16 ha = __float2bfloat16_rn(xa), hb = __float2bfloat16_rn(xb);
    __nv_bfloat16 la = __float2bfloat16_rn(xa - __bfloat162float(ha));
    __nv_bfloat16 lb = __float2bfloat16_rn(xb - __bfloat162float(hb));
    if ((ln & 3) == 0){
      fh[mt][0] = (uint32_t)__bfloat16_as_ushort(ha);
      fh[mt][1] = (uint32_t)__bfloat16_as_ushort(hb);
      fl[mt][0] = (uint32_t)__bfloat16_as_ushort(la);
      fl[mt][1] = (uint32_t)__bfloat16_as_ushort(lb);
    }
  }
  const uint32_t bro = (uint32_t)((ln & 15) + ((ln >> 4) << 4));
  #pragma unroll
  for (int g = 0; g < 4; g++){
    uint32_t bh[4];
    const uint32_t bo = ((64 + bro) * WS + g * 64 + qu * 8) * 2;   // kkp=0 only
    LDSM_X4T(bh, smb + SM_WH + bo);
    #pragma unroll
    for (int mt = 0; mt < 2; mt++){
      MMA16816(acc[mt][g], fh[mt], bh[0], bh[1]);
      MMA16816(acc[mt][g], fl[mt], bh[0], bh[1]);
    }
  }
}

__global__ __launch_bounds__(512, 1)
void lstm_kernel(const float* __restrict__ x, const float* __restrict__ labels,
                 const float* __restrict__ W0, const float* __restrict__ b0,
                 const float* __restrict__ Wl, const float* __restrict__ bl,
                 const float* __restrict__ Wd, const float* __restrict__ bd,
                 float* __restrict__ out, int out_size)
{
  extern __shared__ char smem[];
  const uint32_t smb = smem_to_u32(smem);
  float* biasS = (float*)(smem + SM_BIAS);
  float* lred  = (float*)(smem + SM_LRED);

  const int l    = blockIdx.x >> 1;
  const int half = blockIdx.x & 1;
  const int tid  = threadIdx.x;
  const int w    = tid >> 5;
  const int ln   = tid & 31;
  const int mg   = w & 1;
  const int qu   = w >> 1;
  const int tq   = ln >> 2, tr = ln & 3;
  const int u0   = qu * 8 + tr * 2;

  // ---- build bf16 weights (k: [own h 0..63 | lower/x 64..127]) ----
  for (int idx = tid; idx < 32768; idx += 512){
    int k = idx >> 8, n = idx & 255;
    float wv;
    if (l == 0) wv = (k < 64) ? W0[(1 + k) * 256 + n] : (k == 64 ? W0[n] : 0.0f);
    else {
      const float* Wsrc = Wl + (size_t)(l - 1) * 32768;
      wv = (k < 64) ? Wsrc[(64 + k) * 256 + n] : Wsrc[(k - 64) * 256 + n];
    }
    *(__nv_bfloat16*)(smem + SM_WH + ((size_t)k * WS + n) * 2) = __float2bfloat16_rn(wv);
  }
  {
    const float* bs = (l == 0) ? b0 : bl + (size_t)(l - 1) * 256;
    for (int i = tid; i < 256; i += 512) biasS[i] = bs[i];
  }
  for (int i = tid; i < 2 * A_PLANE / 4; i += 512)
    ((uint32_t*)(smem + SM_A0))[i] = 0u;
  __syncthreads();

  float bsr[4][2];
  #pragma unroll
  for (int g = 0; g < 4; g++)
    #pragma unroll
    for (int j = 0; j < 2; j++) bsr[g][j] = biasS[g * 64 + u0 + j];

  float cst[8];
  #pragma unroll
  for (int i = 0; i < 8; i++) cst[i] = 0.0f;
  float lsum = 0.0f;

  // producer fragment-store constants
  const int p_kk   = qu >> 1;
  const int p_lane = tq * 4 + tr;
  const int p_rg   = (qu & 1) * 2;   // + rh

  for (int t = 0; t < TT; t++){
    float acc[2][4][4];
    #pragma unroll
    for (int mt = 0; mt < 2; mt++)
      #pragma unroll
      for (int g = 0; g < 4; g++)
        #pragma unroll
        for (int ci = 0; ci < 4; ci++) acc[mt][g][ci] = 0.0f;

    // 1. own-h GEMM from smem buf (t&1)
    own_gemm(smem, smb, t & 1, mg, qu, ln, acc);

    // 2+3. acquire lower h, x-slab GEMM (fragments straight from global)
    if (l > 0){
      const int* fp = &g_flag[((l - 1) * 64 + t) * 2 + half];
      unsigned v;
      do { asm volatile("ld.acquire.gpu.b32 %0, [%1];" : "=r"(v) : "l"(fp) : "memory"); } while (v == 0u);
      const uint4* fbase = &g_frag[(size_t)GFIDX(t, half, 0, 0) * 32];
      x_gemm(smb, fbase, mg, qu, ln, acc);
    } else {
      x_gemm_l0(smb, x, t, half, mg, qu, ln, acc);
    }

    // 4. epilogue: gates -> c, h
    float hv[8];
    #pragma unroll
    for (int mt = 0; mt < 2; mt++)
      #pragma unroll
      for (int ci = 0; ci < 4; ci++){
        const int j = ci & 1;
        const int ii = mt * 4 + ci;
        float vi = acc[mt][0][ci] + bsr[0][j];
        float vj = acc[mt][1][ci] + bsr[1][j];
        float vf = acc[mt][2][ci] + bsr[2][j];
        float vo = acc[mt][3][ci] + bsr[3][j];
        float cc = cst[ii] * siga(vf) + siga(vi) * tanha(vj);
        cst[ii] = cc;
        hv[ii] = tanha(cc) * siga(vo);
      }

    // 5. store h (bf16): smem buf (t+1)&1 for own-GEMM + g_frag scatter for upper layer
    const int wb = (t + 1) & 1;
    #pragma unroll
    for (int mt = 0; mt < 2; mt++)
      #pragma unroll
      for (int rh = 0; rh < 2; rh++){
        const int b  = mg * 32 + mt * 16 + tq + rh * 8;
        const int i0 = mt * 4 + rh * 2;
        uint32_t hi0 = __bfloat16_as_ushort(__float2bfloat16_rn(hv[i0]));
        uint32_t hi1 = __bfloat16_as_ushort(__float2bfloat16_rn(hv[i0 + 1]));
        const uint32_t wh = hi0 | (hi1 << 16);
        *(uint32_t*)(smem + SM_A(wb) + (b * AS + u0) * 2) = wh;
        if (l < 63){
          const int rb = mg * 2 + mt;
          uint32_t* wp0 = (uint32_t*)&g_frag[(size_t)GFIDX(t, half, rb, p_kk) * 32 + p_lane];
          wp0[p_rg + rh] = wh;
        }
      }

    __syncthreads();   // orders: h smem stores (next own-GEMM), g_frag stores (release), poll passes (flag reset)

    if (tid == 0){
      if (l > 0){      // reset consumed flag (self-cleaning for graph replays)
        int* cp = &g_flag[((l - 1) * 64 + t) * 2 + half];
        asm volatile("st.relaxed.gpu.b32 [%0], %1;" :: "l"(cp), "r"(0) : "memory");
      }
      if (l < 63){     // publish h(t): bar.sync + release gives cumulative ordering
        int* fp = &g_flag[(l * 64 + t) * 2 + half];
        asm volatile("st.release.gpu.b32 [%0], %1;" :: "l"(fp), "r"(1) : "memory");
      }
    }

    if (l == 63 && tid < 64){
      // fused dense(1) + relu + loss partial
      const int r = tid;
      float accd = bd[t];
      const uint32_t* hp = (const uint32_t*)(smem + SM_A(wb) + r * AS * 2);
      const float* wd = &Wd[(size_t)t * 64];
      #pragma unroll 8
      for (int i2 = 0; i2 < 32; i2++){
        uint32_t hh = hp[i2];
        float h0 = __bfloat162float(__ushort_as_bfloat16((unsigned short)(hh & 0xFFFF)));
        float h1 = __bfloat162float(__ushort_as_bfloat16((unsigned short)(hh >> 16)));
        accd += h0 * wd[2 * i2] + h1 * wd[2 * i2 + 1];
      }
      float pred = fmaxf(accd, 0.0f);
      const int gb = half * 64 + r;
      if (out_size >= 8192) out[(size_t)gb * TT + t] = pred;
      float d = labels[(size_t)gb * TT + t] - pred;
      lsum += d * d;
    }
  }

  // loss: (63,0) -> (63,1) handshake, deterministic fixed-order sums
  if (l == 63){
    if (tid < 64) lred[tid] = lsum;
    __syncthreads();
    if (tid == 0){
      float s = 0.0f;
      for (int i = 0; i < 64; i++) s += lred[i];
      int* lf = &g_flag[FLAG_LOSS];
      if (half == 0){
        g_losspart0 = s;
        asm volatile("st.release.gpu.b32 [%0], %1;" :: "l"(lf), "r"(1) : "memory");
      } else {
        unsigned v;
        do { asm volatile("ld.acquire.gpu.b32 %0, [%1];" : "=r"(v) : "l"(lf) : "memory"); } while (v == 0u);
        float loss = (g_losspart0 + s) * (1.0f / 8192.0f);
        if (out_size >= 8193)   out[8192] = loss;
        else if (out_size == 1) out[0]   = loss;
        asm volatile("st.relaxed.gpu.b32 [%0], %1;" :: "l"(lf), "r"(0) : "memory");
      }
    }
  }
}

extern "C" void kernel_launch(void* const* d_in, const int* in_sizes, int n_in,
                              void* d_out, int out_size)
{
  const float* x      = (const float*)d_in[0];
  const float* labels = (const float*)d_in[1];
  const float* W0     = (const float*)d_in[2];
  const float* b0     = (const float*)d_in[3];
  const float* Wl     = (const float*)d_in[4];
  const float* bl     = (const float*)d_in[5];
  const float* Wd     = (const float*)d_in[6];
  const float* bd     = (const float*)d_in[7];
  float* out = (float*)d_out;

  cudaFuncSetAttribute(lstm_kernel, cudaFuncAttributeMaxDynamicSharedMemorySize, SMEM_DYN);
  lstm_kernel<<<128, 512, SMEM_DYN>>>(x, labels, W0, b0, Wl, bl, Wd, bd, out, out_size);
}